// round 2
// baseline (speedup 1.0000x reference)
#include <cuda_runtime.h>
#include <math.h>
#include <stdint.h>

#define NB   8
#define CCH  640
#define HW   1024
#define C3   1920
#define NH   8
#define DH   80
#define CTXL 77
#define DCTX 512
#define F8   5120
#define F4   2560
#define MTOT (NB*HW)   // 8192

// -------- scratch (device globals; no allocation allowed) --------
__device__ float g_gnt [NB*HW*CCH];    // groupnorm output, [n,p,c] layout
__device__ float g_xseq[NB*HW*CCH];    // running activation [n,p,c]
__device__ float g_t   [NB*HW*CCH];    // layernorm output
__device__ float g_qkv [NB*HW*C3];     // fused qkv
__device__ float g_attn[NB*HW*CCH];    // attention output
__device__ float g_q   [NB*HW*CCH];    // cross-attn q
__device__ float g_ck  [NB*CTXL*CCH];  // cross-attn k
__device__ float g_cv  [NB*CTXL*CCH];  // cross-attn v
__device__ float g_h1  [NB*HW*F8];     // lin1 output
__device__ float g_gg  [NB*HW*F4];     // geglu output
__device__ float g_w1t [CCH*CCH];      // conv1_w transposed -> [in,out]
__device__ float g_w2t [CCH*CCH];      // co_w transposed -> [in,out]

// -------- small weight transpose: wt[c*C+o] = w[o*C+c] --------
__global__ void transpose_w(const float* __restrict__ w, float* __restrict__ wt) {
    int idx = blockIdx.x * blockDim.x + threadIdx.x;
    if (idx < CCH * CCH) {
        int o = idx / CCH, c = idx % CCH;
        wt[c * CCH + o] = w[idx];
    }
}

// -------- GroupNorm (32 groups of 20 ch), writes transposed [n,p,c] --------
__global__ __launch_bounds__(256) void gn_kernel(
    const float* __restrict__ x, const float* __restrict__ s,
    const float* __restrict__ b, float* __restrict__ out)
{
    const int g = blockIdx.x;   // 0..31
    const int n = blockIdx.y;   // 0..7
    const int cpg = CCH / 32;   // 20
    const int cnt = cpg * HW;   // 20480
    const float* xp = x + ((size_t)n * CCH + (size_t)g * cpg) * HW;

    float sum = 0.f, sq = 0.f;
    for (int i = threadIdx.x; i < cnt; i += 256) {
        float v = xp[i]; sum += v; sq += v * v;
    }
    __shared__ float ss[8], sv[8];
    int lane = threadIdx.x & 31, wid = threadIdx.x >> 5;
    #pragma unroll
    for (int o = 16; o > 0; o >>= 1) {
        sum += __shfl_xor_sync(0xffffffffu, sum, o);
        sq  += __shfl_xor_sync(0xffffffffu, sq,  o);
    }
    if (lane == 0) { ss[wid] = sum; sv[wid] = sq; }
    __syncthreads();
    if (threadIdx.x == 0) {
        float ts = 0.f, tq = 0.f;
        #pragma unroll
        for (int w = 0; w < 8; w++) { ts += ss[w]; tq += sv[w]; }
        ss[0] = ts; sv[0] = tq;
    }
    __syncthreads();
    float mu  = ss[0] / (float)cnt;
    float var = sv[0] / (float)cnt - mu * mu;
    float inv = rsqrtf(var + 1e-6f);

    for (int i = threadIdx.x; i < cnt; i += 256) {
        int cl = i >> 10, p = i & 1023;
        int c  = g * cpg + cl;
        float v = (xp[i] - mu) * inv * s[c] + b[c];
        out[((size_t)n * HW + p) * CCH + c] = v;
    }
}

// -------- LayerNorm over last dim 640 (one block per row) --------
__global__ __launch_bounds__(256) void ln_kernel(
    const float* __restrict__ x, const float* __restrict__ s,
    const float* __restrict__ b, float* __restrict__ out)
{
    const size_t row = blockIdx.x;
    const float* xp = x + row * CCH;
    float sum = 0.f, sq = 0.f;
    for (int i = threadIdx.x; i < CCH; i += 256) {
        float v = xp[i]; sum += v; sq += v * v;
    }
    __shared__ float ss[8], sv[8];
    int lane = threadIdx.x & 31, wid = threadIdx.x >> 5;
    #pragma unroll
    for (int o = 16; o > 0; o >>= 1) {
        sum += __shfl_xor_sync(0xffffffffu, sum, o);
        sq  += __shfl_xor_sync(0xffffffffu, sq,  o);
    }
    if (lane == 0) { ss[wid] = sum; sv[wid] = sq; }
    __syncthreads();
    if (threadIdx.x == 0) {
        float ts = 0.f, tq = 0.f;
        #pragma unroll
        for (int w = 0; w < 8; w++) { ts += ss[w]; tq += sv[w]; }
        ss[0] = ts; sv[0] = tq;
    }
    __syncthreads();
    float mu  = ss[0] / (float)CCH;
    float var = sv[0] / (float)CCH - mu * mu;
    float inv = rsqrtf(var + 1e-5f);
    for (int i = threadIdx.x; i < CCH; i += 256)
        out[row * CCH + i] = (xp[i] - mu) * inv * s[i] + b[i];
}

// -------- generic tiled fp32 GEMM: C = A[MxK] @ B[KxN] (+bias) (+res) --------
// Requires: K % 16 == 0, N % 64 == 0 (true for all call sites).
// out_trans: m = nb*1024 + p, store/residual index = (nb*N + n)*1024 + p
__global__ __launch_bounds__(256) void gemm_kernel(
    const float* __restrict__ A, const float* __restrict__ B,
    const float* __restrict__ bias, const float* __restrict__ R,
    float* __restrict__ Cout, int M, int N, int K, int out_trans)
{
    __shared__ float As[64][17];
    __shared__ float Bs[16][65];
    const int tid = threadIdx.y * 16 + threadIdx.x;
    const int m0 = blockIdx.y * 64;
    const int n0 = blockIdx.x * 64;
    float acc[4][4] = {};

    // A-stage mapping: thread loads 4 consecutive k's of one row
    const int a_mm = (tid * 4) >> 4;        // 0..63
    const int a_kk = (tid * 4) & 15;        // 0,4,8,12
    // B-stage mapping: thread loads 4 consecutive n's of one k-row
    const int b_kk = (tid * 4) >> 6;        // 0..15
    const int b_nn = (tid * 4) & 63;        // 0..60 step 4

    for (int k0 = 0; k0 < K; k0 += 16) {
        {
            int m = m0 + a_mm;
            float4 av = make_float4(0.f, 0.f, 0.f, 0.f);
            if (m < M)
                av = *(const float4*)&A[(size_t)m * K + k0 + a_kk];
            As[a_mm][a_kk + 0] = av.x;
            As[a_mm][a_kk + 1] = av.y;
            As[a_mm][a_kk + 2] = av.z;
            As[a_mm][a_kk + 3] = av.w;
        }
        {
            float4 bv = *(const float4*)&B[(size_t)(k0 + b_kk) * N + n0 + b_nn];
            Bs[b_kk][b_nn + 0] = bv.x;
            Bs[b_kk][b_nn + 1] = bv.y;
            Bs[b_kk][b_nn + 2] = bv.z;
            Bs[b_kk][b_nn + 3] = bv.w;
        }
        __syncthreads();
        #pragma unroll
        for (int kk = 0; kk < 16; kk++) {
            float a[4], bb[4];
            #pragma unroll
            for (int i = 0; i < 4; i++) a[i]  = As[threadIdx.y * 4 + i][kk];
            #pragma unroll
            for (int j = 0; j < 4; j++) bb[j] = Bs[kk][threadIdx.x * 4 + j];
            #pragma unroll
            for (int i = 0; i < 4; i++)
                #pragma unroll
                for (int j = 0; j < 4; j++)
                    acc[i][j] += a[i] * bb[j];
        }
        __syncthreads();
    }

    #pragma unroll
    for (int i = 0; i < 4; i++) {
        int m = m0 + threadIdx.y * 4 + i;
        if (m >= M) continue;
        #pragma unroll
        for (int j = 0; j < 4; j++) {
            int n = n0 + threadIdx.x * 4 + j;
            float v = acc[i][j];
            if (bias) v += bias[n];
            size_t idx;
            if (out_trans) {
                int nb = m >> 10, p = m & 1023;
                idx = ((size_t)nb * N + n) * 1024 + p;
            } else {
                idx = (size_t)m * N + n;
            }
            if (R) v += R[idx];
            Cout[idx] = v;
        }
    }
}

// -------- fused softmax attention, one block per (q, head, batch) --------
__global__ __launch_bounds__(128) void attn_kernel(
    const float* __restrict__ Q, const float* __restrict__ K,
    const float* __restrict__ V, float* __restrict__ O,
    int seq_kv, int qs, int ks, int vs, int os,
    long long qbs, long long kbs, long long vbs, long long obs)
{
    const int q = blockIdx.x, h = blockIdx.y, b = blockIdx.z;
    const float* qp = Q + (size_t)b * qbs + (size_t)q * qs + h * DH;
    const float* kp = K + (size_t)b * kbs + h * DH;
    const float* vp = V + (size_t)b * vbs + h * DH;
    float*       op = O + (size_t)b * obs + (size_t)q * os + h * DH;

    __shared__ float sq[DH];
    __shared__ float sc[1024];
    __shared__ float red[4];
    const int tid = threadIdx.x;
    if (tid < DH) sq[tid] = qp[tid];
    __syncthreads();

    const float scale = 0.11180339887498949f;  // 1/sqrt(80)
    for (int k = tid; k < seq_kv; k += 128) {
        const float* kr = kp + (size_t)k * ks;
        float s = 0.f;
        #pragma unroll
        for (int d = 0; d < DH; d++) s += sq[d] * kr[d];
        sc[k] = s * scale;
    }
    __syncthreads();

    // max
    float m = -1e30f;
    for (int k = tid; k < seq_kv; k += 128) m = fmaxf(m, sc[k]);
    #pragma unroll
    for (int o = 16; o > 0; o >>= 1) m = fmaxf(m, __shfl_xor_sync(0xffffffffu, m, o));
    if ((tid & 31) == 0) red[tid >> 5] = m;
    __syncthreads();
    float mx = fmaxf(fmaxf(red[0], red[1]), fmaxf(red[2], red[3]));
    __syncthreads();

    // exp + sum
    float sum = 0.f;
    for (int k = tid; k < seq_kv; k += 128) {
        float e = __expf(sc[k] - mx);
        sc[k] = e; sum += e;
    }
    #pragma unroll
    for (int o = 16; o > 0; o >>= 1) sum += __shfl_xor_sync(0xffffffffu, sum, o);
    if ((tid & 31) == 0) red[tid >> 5] = sum;
    __syncthreads();
    float inv = 1.f / (red[0] + red[1] + red[2] + red[3]);

    // weighted sum of V: thread d accumulates over all keys
    if (tid < DH) {
        float acc = 0.f;
        for (int k = 0; k < seq_kv; k++)
            acc += sc[k] * vp[(size_t)k * vs + tid];
        op[tid] = acc * inv;
    }
}

// -------- GeGLU: g[m,j] = h1[m,j] * gelu_exact(h1[m,2560+j]) --------
__global__ __launch_bounds__(256) void geglu_kernel(
    const float* __restrict__ h1, float* __restrict__ g)
{
    size_t i = (size_t)blockIdx.x * 256 + threadIdx.x;
    if (i < (size_t)MTOT * F4) {
        size_t row = i / F4, j = i % F4;
        float a  = h1[row * F8 + j];
        float x  = h1[row * F8 + F4 + j];
        float ge = 0.5f * x * (1.0f + erff(x * 0.70710678118654752f));
        g[i] = a * ge;
    }
}

extern "C" void kernel_launch(void* const* d_in, const int* in_sizes, int n_in,
                              void* d_out, int out_size)
{
    const float* x       = (const float*)d_in[0];
    const float* context = (const float*)d_in[1];
    const float* gn_s    = (const float*)d_in[2];
    const float* gn_b    = (const float*)d_in[3];
    const float* conv1_w = (const float*)d_in[4];
    const float* conv1_b = (const float*)d_in[5];
    const float* ln1_s   = (const float*)d_in[6];
    const float* ln1_b   = (const float*)d_in[7];
    const float* sa_in_w = (const float*)d_in[8];
    const float* sa_out_w= (const float*)d_in[9];
    const float* sa_out_b= (const float*)d_in[10];
    const float* ln2_s   = (const float*)d_in[11];
    const float* ln2_b   = (const float*)d_in[12];
    const float* ca_q_w  = (const float*)d_in[13];
    const float* ca_k_w  = (const float*)d_in[14];
    const float* ca_v_w  = (const float*)d_in[15];
    const float* ca_out_w= (const float*)d_in[16];
    const float* ca_out_b= (const float*)d_in[17];
    const float* ln3_s   = (const float*)d_in[18];
    const float* ln3_b   = (const float*)d_in[19];
    const float* lin1_w  = (const float*)d_in[20];
    const float* lin1_b  = (const float*)d_in[21];
    const float* lin2_w  = (const float*)d_in[22];
    const float* lin2_b  = (const float*)d_in[23];
    const float* co_w    = (const float*)d_in[24];
    const float* co_b    = (const float*)d_in[25];
    float* out = (float*)d_out;

    float *gnt, *xseq, *t, *qkv, *attn, *qb, *ck, *cv, *h1, *gg, *w1t, *w2t;
    cudaGetSymbolAddress((void**)&gnt,  g_gnt);
    cudaGetSymbolAddress((void**)&xseq, g_xseq);
    cudaGetSymbolAddress((void**)&t,    g_t);
    cudaGetSymbolAddress((void**)&qkv,  g_qkv);
    cudaGetSymbolAddress((void**)&attn, g_attn);
    cudaGetSymbolAddress((void**)&qb,   g_q);
    cudaGetSymbolAddress((void**)&ck,   g_ck);
    cudaGetSymbolAddress((void**)&cv,   g_cv);
    cudaGetSymbolAddress((void**)&h1,   g_h1);
    cudaGetSymbolAddress((void**)&gg,   g_gg);
    cudaGetSymbolAddress((void**)&w1t,  g_w1t);
    cudaGetSymbolAddress((void**)&w2t,  g_w2t);

    dim3 blk(16, 16);

    // weight transposes ([out,in] -> [in,out])
    transpose_w<<<(CCH * CCH + 255) / 256, 256>>>(conv1_w, w1t);
    transpose_w<<<(CCH * CCH + 255) / 256, 256>>>(co_w,    w2t);

    // GroupNorm (writes [n,p,c])
    gn_kernel<<<dim3(32, NB), 256>>>(x, gn_s, gn_b, gnt);

    // conv1 (1x1) -> xseq [n,p,c]
    gemm_kernel<<<dim3(CCH/64, MTOT/64), blk>>>(gnt, w1t, conv1_b, nullptr, xseq,
                                                MTOT, CCH, CCH, 0);

    // ---- self-attention ----
    ln_kernel<<<MTOT, 256>>>(xseq, ln1_s, ln1_b, t);
    gemm_kernel<<<dim3(C3/64, MTOT/64), blk>>>(t, sa_in_w, nullptr, nullptr, qkv,
                                               MTOT, C3, CCH, 0);
    attn_kernel<<<dim3(HW, NH, NB), 128>>>(qkv, qkv + CCH, qkv + 2 * CCH, attn,
                                           HW, C3, C3, C3, CCH,
                                           (long long)HW * C3, (long long)HW * C3,
                                           (long long)HW * C3, (long long)HW * CCH);
    gemm_kernel<<<dim3(CCH/64, MTOT/64), blk>>>(attn, sa_out_w, sa_out_b, xseq, xseq,
                                                MTOT, CCH, CCH, 0);

    // ---- cross-attention ----
    ln_kernel<<<MTOT, 256>>>(xseq, ln2_s, ln2_b, t);
    gemm_kernel<<<dim3(CCH/64, MTOT/64), blk>>>(t, ca_q_w, nullptr, nullptr, qb,
                                                MTOT, CCH, CCH, 0);
    gemm_kernel<<<dim3(CCH/64, (NB*CTXL + 63)/64), blk>>>(context, ca_k_w, nullptr, nullptr, ck,
                                                          NB * CTXL, CCH, DCTX, 0);
    gemm_kernel<<<dim3(CCH/64, (NB*CTXL + 63)/64), blk>>>(context, ca_v_w, nullptr, nullptr, cv,
                                                          NB * CTXL, CCH, DCTX, 0);
    attn_kernel<<<dim3(HW, NH, NB), 128>>>(qb, ck, cv, attn,
                                           CTXL, CCH, CCH, CCH, CCH,
                                           (long long)HW * CCH, (long long)CTXL * CCH,
                                           (long long)CTXL * CCH, (long long)HW * CCH);
    gemm_kernel<<<dim3(CCH/64, MTOT/64), blk>>>(attn, ca_out_w, ca_out_b, xseq, xseq,
                                                MTOT, CCH, CCH, 0);

    // ---- GeGLU FFN ----
    ln_kernel<<<MTOT, 256>>>(xseq, ln3_s, ln3_b, t);
    gemm_kernel<<<dim3(F8/64, MTOT/64), blk>>>(t, lin1_w, lin1_b, nullptr, h1,
                                               MTOT, F8, CCH, 0);
    geglu_kernel<<<(unsigned)(((size_t)MTOT * F4 + 255) / 256), 256>>>(h1, gg);
    gemm_kernel<<<dim3(CCH/64, MTOT/64), blk>>>(gg, lin2_w, lin2_b, xseq, xseq,
                                                MTOT, CCH, F4, 0);

    // ---- output conv + long residual (transposed store back to [n,c,h,w]) ----
    gemm_kernel<<<dim3(CCH/64, MTOT/64), blk>>>(xseq, w2t, co_b, x, out,
                                                MTOT, CCH, CCH, 1);
}

// round 4
// speedup vs baseline: 4.6446x; 4.6446x over previous
#include <cuda_runtime.h>
#include <math.h>
#include <stdint.h>

#define NB   8
#define CCH  640
#define HW   1024
#define C3   1920
#define NH   8
#define DH   80
#define CTXL 77
#define DCTX 512
#define F8   5120
#define F4   2560
#define MTOT (NB*HW)   // 8192

// attention tiling
#define QT 64
#define KT 64
#define QP 81   // Q/K/V smem row pitch (odd -> conflict-free-ish)
#define PP 65   // P smem row pitch
#define SMEM_ATTN ((3*QT*QP + QT*PP)*4)

// -------- scratch (device globals; no allocation allowed) --------
__device__ float g_gnt [NB*HW*CCH];
__device__ float g_xseq[NB*HW*CCH];
__device__ float g_t   [NB*HW*CCH];
__device__ float g_qkv [NB*HW*C3];
__device__ float g_attn[NB*HW*CCH];
__device__ float g_q   [NB*HW*CCH];
__device__ float g_ck  [NB*CTXL*CCH];
__device__ float g_cv  [NB*CTXL*CCH];
__device__ float g_h1  [NB*HW*F8];
__device__ float g_gg  [NB*HW*F4];
__device__ float g_w1t [CCH*CCH];
__device__ float g_w2t [CCH*CCH];

// -------- small weight transpose: wt[c*C+o] = w[o*C+c] --------
__global__ void transpose_w(const float* __restrict__ w, float* __restrict__ wt) {
    int idx = blockIdx.x * blockDim.x + threadIdx.x;
    if (idx < CCH * CCH) {
        int o = idx / CCH, c = idx % CCH;
        wt[c * CCH + o] = w[idx];
    }
}

// -------- GroupNorm (32 groups of 20 ch), writes transposed [n,p,c] --------
__global__ __launch_bounds__(256) void gn_kernel(
    const float* __restrict__ x, const float* __restrict__ s,
    const float* __restrict__ b, float* __restrict__ out)
{
    const int g = blockIdx.x;
    const int n = blockIdx.y;
    const int cpg = CCH / 32;   // 20
    const int cnt = cpg * HW;   // 20480
    const float* xp = x + ((size_t)n * CCH + (size_t)g * cpg) * HW;

    float sum = 0.f, sq = 0.f;
    for (int i = threadIdx.x; i < cnt; i += 256) {
        float v = xp[i]; sum += v; sq += v * v;
    }
    __shared__ float ss[8], sv[8];
    int lane = threadIdx.x & 31, wid = threadIdx.x >> 5;
    #pragma unroll
    for (int o = 16; o > 0; o >>= 1) {
        sum += __shfl_xor_sync(0xffffffffu, sum, o);
        sq  += __shfl_xor_sync(0xffffffffu, sq,  o);
    }
    if (lane == 0) { ss[wid] = sum; sv[wid] = sq; }
    __syncthreads();
    if (threadIdx.x == 0) {
        float ts = 0.f, tq = 0.f;
        #pragma unroll
        for (int w = 0; w < 8; w++) { ts += ss[w]; tq += sv[w]; }
        ss[0] = ts; sv[0] = tq;
    }
    __syncthreads();
    float mu  = ss[0] / (float)cnt;
    float var = sv[0] / (float)cnt - mu * mu;
    float inv = rsqrtf(var + 1e-6f);

    for (int i = threadIdx.x; i < cnt; i += 256) {
        int cl = i >> 10, p = i & 1023;
        int c  = g * cpg + cl;
        float v = (xp[i] - mu) * inv * s[c] + b[c];
        out[((size_t)n * HW + p) * CCH + c] = v;
    }
}

// -------- LayerNorm over last dim 640 --------
__global__ __launch_bounds__(256) void ln_kernel(
    const float* __restrict__ x, const float* __restrict__ s,
    const float* __restrict__ b, float* __restrict__ out)
{
    const size_t row = blockIdx.x;
    const float* xp = x + row * CCH;
    float sum = 0.f, sq = 0.f;
    for (int i = threadIdx.x; i < CCH; i += 256) {
        float v = xp[i]; sum += v; sq += v * v;
    }
    __shared__ float ss[8], sv[8];
    int lane = threadIdx.x & 31, wid = threadIdx.x >> 5;
    #pragma unroll
    for (int o = 16; o > 0; o >>= 1) {
        sum += __shfl_xor_sync(0xffffffffu, sum, o);
        sq  += __shfl_xor_sync(0xffffffffu, sq,  o);
    }
    if (lane == 0) { ss[wid] = sum; sv[wid] = sq; }
    __syncthreads();
    if (threadIdx.x == 0) {
        float ts = 0.f, tq = 0.f;
        #pragma unroll
        for (int w = 0; w < 8; w++) { ts += ss[w]; tq += sv[w]; }
        ss[0] = ts; sv[0] = tq;
    }
    __syncthreads();
    float mu  = ss[0] / (float)CCH;
    float var = sv[0] / (float)CCH - mu * mu;
    float inv = rsqrtf(var + 1e-5f);
    for (int i = threadIdx.x; i < CCH; i += 256)
        out[row * CCH + i] = (xp[i] - mu) * inv * s[i] + b[i];
}

// -------- tiled fp32 GEMM, 128x64 tile, 8x4/thread, double-buffered --------
// Requires K % 16 == 0, N % 64 == 0.
__global__ __launch_bounds__(256) void gemm_kernel(
    const float* __restrict__ A, const float* __restrict__ B,
    const float* __restrict__ bias, const float* __restrict__ R,
    float* __restrict__ Cout, int M, int N, int K, int out_trans)
{
    __shared__ float As[2][128][17];
    __shared__ float Bs[2][16][65];
    const int tid = threadIdx.x;
    const int ty = tid >> 4, tx = tid & 15;
    const int m0 = blockIdx.y * 128, n0 = blockIdx.x * 64;

    const int a_m = tid >> 1;
    const int a_k = (tid & 1) * 8;
    const int b_k = tid >> 4;
    const int b_n = (tid & 15) * 4;

    float acc[8][4] = {};

    const int nk = K >> 4;
    // prologue tile 0
    {
        int mg = m0 + a_m;
        float4 v0 = make_float4(0.f,0.f,0.f,0.f), v1 = v0;
        if (mg < M) {
            v0 = *(const float4*)&A[(size_t)mg * K + a_k];
            v1 = *(const float4*)&A[(size_t)mg * K + a_k + 4];
        }
        As[0][a_m][a_k+0]=v0.x; As[0][a_m][a_k+1]=v0.y; As[0][a_m][a_k+2]=v0.z; As[0][a_m][a_k+3]=v0.w;
        As[0][a_m][a_k+4]=v1.x; As[0][a_m][a_k+5]=v1.y; As[0][a_m][a_k+6]=v1.z; As[0][a_m][a_k+7]=v1.w;
        float4 bv = *(const float4*)&B[(size_t)b_k * N + n0 + b_n];
        Bs[0][b_k][b_n+0]=bv.x; Bs[0][b_k][b_n+1]=bv.y; Bs[0][b_k][b_n+2]=bv.z; Bs[0][b_k][b_n+3]=bv.w;
    }
    __syncthreads();

    for (int t = 0; t < nk; t++) {
        const int cur = t & 1, nxt = cur ^ 1;
        if (t + 1 < nk) {
            int k0 = (t + 1) << 4;
            int mg = m0 + a_m;
            float4 v0 = make_float4(0.f,0.f,0.f,0.f), v1 = v0;
            if (mg < M) {
                v0 = *(const float4*)&A[(size_t)mg * K + k0 + a_k];
                v1 = *(const float4*)&A[(size_t)mg * K + k0 + a_k + 4];
            }
            As[nxt][a_m][a_k+0]=v0.x; As[nxt][a_m][a_k+1]=v0.y; As[nxt][a_m][a_k+2]=v0.z; As[nxt][a_m][a_k+3]=v0.w;
            As[nxt][a_m][a_k+4]=v1.x; As[nxt][a_m][a_k+5]=v1.y; As[nxt][a_m][a_k+6]=v1.z; As[nxt][a_m][a_k+7]=v1.w;
            float4 bv = *(const float4*)&B[(size_t)(k0 + b_k) * N + n0 + b_n];
            Bs[nxt][b_k][b_n+0]=bv.x; Bs[nxt][b_k][b_n+1]=bv.y; Bs[nxt][b_k][b_n+2]=bv.z; Bs[nxt][b_k][b_n+3]=bv.w;
        }
        #pragma unroll
        for (int kk = 0; kk < 16; kk++) {
            float a[8], bb[4];
            #pragma unroll
            for (int i = 0; i < 8; i++) a[i] = As[cur][ty*8+i][kk];
            #pragma unroll
            for (int j = 0; j < 4; j++) bb[j] = Bs[cur][kk][tx*4+j];
            #pragma unroll
            for (int i = 0; i < 8; i++)
                #pragma unroll
                for (int j = 0; j < 4; j++)
                    acc[i][j] += a[i] * bb[j];
        }
        __syncthreads();
    }

    #pragma unroll
    for (int i = 0; i < 8; i++) {
        int m = m0 + ty*8 + i;
        if (m >= M) continue;
        #pragma unroll
        for (int j = 0; j < 4; j++) {
            int n = n0 + tx*4 + j;
            float v = acc[i][j];
            if (bias) v += bias[n];
            size_t idx;
            if (out_trans) {
                int nb = m >> 10, p = m & 1023;
                idx = ((size_t)nb * N + n) * 1024 + p;
            } else {
                idx = (size_t)m * N + n;
            }
            if (R) v += R[idx];
            Cout[idx] = v;
        }
    }
}

// -------- flash-style tiled attention --------
// block: 256 threads (16x16), 64-query tile, K/V staged in 64-row smem tiles,
// online softmax. rows owned per ty (4 rows), shuffle-reduce over 16-lane tx group.
__global__ __launch_bounds__(256) void fattn_kernel(
    const float* __restrict__ Q, const float* __restrict__ K,
    const float* __restrict__ V, float* __restrict__ O,
    int seq_kv, int qs, int ks, int vs, int os,
    long long qbs, long long kbs, long long vbs, long long obs)
{
    extern __shared__ float sm[];
    float* Qs = sm;                 // QT x QP
    float* Ks = Qs + QT*QP;         // KT x QP
    float* Vs = Ks + KT*QP;         // KT x QP
    float* Ps = Vs + KT*QP;         // QT x PP

    const int qt = blockIdx.x, h = blockIdx.y, b = blockIdx.z;
    const int tid = threadIdx.x;
    const int ty = tid >> 4, tx = tid & 15;

    const float* qp = Q + (size_t)b * qbs + (size_t)h * DH;
    const float* kp = K + (size_t)b * kbs + (size_t)h * DH;
    const float* vp = V + (size_t)b * vbs + (size_t)h * DH;
    float*       op = O + (size_t)b * obs + (size_t)h * DH;

    // load Q tile
    for (int i = tid; i < QT*DH; i += 256) {
        int r = i / DH, d = i - r*DH;
        Qs[r*QP + d] = qp[(size_t)(qt*QT + r) * qs + d];
    }

    float m[4], l[4], o[4][5];
    #pragma unroll
    for (int i = 0; i < 4; i++) {
        m[i] = -1e30f; l[i] = 0.f;
        #pragma unroll
        for (int j = 0; j < 5; j++) o[i][j] = 0.f;
    }

    const float scale = 0.11180339887498949f;  // 1/sqrt(80)
    const int ntile = (seq_kv + KT - 1) / KT;

    for (int t = 0; t < ntile; t++) {
        const int k0 = t * KT;
        __syncthreads();  // prev PV done (and Qs ready at t=0)
        for (int i = tid; i < KT*DH; i += 256) {
            int r = i / DH, d = i - r*DH;
            int kg = k0 + r;
            float kv = 0.f, vv = 0.f;
            if (kg < seq_kv) {
                kv = kp[(size_t)kg * ks + d];
                vv = vp[(size_t)kg * vs + d];
            }
            Ks[r*QP + d] = kv;
            Vs[r*QP + d] = vv;
        }
        __syncthreads();

        // S = Q K^T : rows ty*4+i, cols tx*4+j
        float s[4][4] = {};
        for (int d = 0; d < DH; d++) {
            float qv[4], kv[4];
            #pragma unroll
            for (int i = 0; i < 4; i++) qv[i] = Qs[(ty*4+i)*QP + d];
            #pragma unroll
            for (int j = 0; j < 4; j++) kv[j] = Ks[(tx*4+j)*QP + d];
            #pragma unroll
            for (int i = 0; i < 4; i++)
                #pragma unroll
                for (int j = 0; j < 4; j++)
                    s[i][j] += qv[i] * kv[j];
        }
        #pragma unroll
        for (int i = 0; i < 4; i++)
            #pragma unroll
            for (int j = 0; j < 4; j++) {
                s[i][j] *= scale;
                if (k0 + tx*4 + j >= seq_kv) s[i][j] = -1e30f;
            }

        // online softmax per owned row
        #pragma unroll
        for (int i = 0; i < 4; i++) {
            float mt = fmaxf(fmaxf(s[i][0], s[i][1]), fmaxf(s[i][2], s[i][3]));
            #pragma unroll
            for (int off = 8; off > 0; off >>= 1)
                mt = fmaxf(mt, __shfl_xor_sync(0xffffffffu, mt, off));
            float mn = fmaxf(m[i], mt);
            float f  = __expf(m[i] - mn);
            m[i] = mn;
            float rs = 0.f;
            #pragma unroll
            for (int j = 0; j < 4; j++) {
                float p = __expf(s[i][j] - mn);
                s[i][j] = p;
                rs += p;
            }
            #pragma unroll
            for (int off = 8; off > 0; off >>= 1)
                rs += __shfl_xor_sync(0xffffffffu, rs, off);
            l[i] = l[i] * f + rs;
            #pragma unroll
            for (int j = 0; j < 5; j++) o[i][j] *= f;
        }

        #pragma unroll
        for (int i = 0; i < 4; i++)
            #pragma unroll
            for (int j = 0; j < 4; j++)
                Ps[(ty*4+i)*PP + tx*4+j] = s[i][j];
        __syncthreads();

        // O += P V : rows ty*4+i, cols tx*5+j
        for (int k = 0; k < KT; k++) {
            float pv[4], vv[5];
            #pragma unroll
            for (int i = 0; i < 4; i++) pv[i] = Ps[(ty*4+i)*PP + k];
            #pragma unroll
            for (int j = 0; j < 5; j++) vv[j] = Vs[k*QP + tx*5+j];
            #pragma unroll
            for (int i = 0; i < 4; i++)
                #pragma unroll
                for (int j = 0; j < 5; j++)
                    o[i][j] += pv[i] * vv[j];
        }
    }

    #pragma unroll
    for (int i = 0; i < 4; i++) {
        float inv = 1.f / l[i];
        int qg = qt*QT + ty*4 + i;
        #pragma unroll
        for (int j = 0; j < 5; j++)
            op[(size_t)qg * os + tx*5 + j] = o[i][j] * inv;
    }
}

// -------- GeGLU --------
__global__ __launch_bounds__(256) void geglu_kernel(
    const float* __restrict__ h1, float* __restrict__ g)
{
    size_t i = (size_t)blockIdx.x * 256 + threadIdx.x;
    if (i < (size_t)MTOT * F4) {
        size_t row = i / F4, j = i % F4;
        float a  = h1[row * F8 + j];
        float x  = h1[row * F8 + F4 + j];
        float ge = 0.5f * x * (1.0f + erff(x * 0.70710678118654752f));
        g[i] = a * ge;
    }
}

extern "C" void kernel_launch(void* const* d_in, const int* in_sizes, int n_in,
                              void* d_out, int out_size)
{
    const float* x       = (const float*)d_in[0];
    const float* context = (const float*)d_in[1];
    const float* gn_s    = (const float*)d_in[2];
    const float* gn_b    = (const float*)d_in[3];
    const float* conv1_w = (const float*)d_in[4];
    const float* conv1_b = (const float*)d_in[5];
    const float* ln1_s   = (const float*)d_in[6];
    const float* ln1_b   = (const float*)d_in[7];
    const float* sa_in_w = (const float*)d_in[8];
    const float* sa_out_w= (const float*)d_in[9];
    const float* sa_out_b= (const float*)d_in[10];
    const float* ln2_s   = (const float*)d_in[11];
    const float* ln2_b   = (const float*)d_in[12];
    const float* ca_q_w  = (const float*)d_in[13];
    const float* ca_k_w  = (const float*)d_in[14];
    const float* ca_v_w  = (const float*)d_in[15];
    const float* ca_out_w= (const float*)d_in[16];
    const float* ca_out_b= (const float*)d_in[17];
    const float* ln3_s   = (const float*)d_in[18];
    const float* ln3_b   = (const float*)d_in[19];
    const float* lin1_w  = (const float*)d_in[20];
    const float* lin1_b  = (const float*)d_in[21];
    const float* lin2_w  = (const float*)d_in[22];
    const float* lin2_b  = (const float*)d_in[23];
    const float* co_w    = (const float*)d_in[24];
    const float* co_b    = (const float*)d_in[25];
    float* out = (float*)d_out;

    float *gnt, *xseq, *t, *qkv, *attn, *qb, *ck, *cv, *h1, *gg, *w1t, *w2t;
    cudaGetSymbolAddress((void**)&gnt,  g_gnt);
    cudaGetSymbolAddress((void**)&xseq, g_xseq);
    cudaGetSymbolAddress((void**)&t,    g_t);
    cudaGetSymbolAddress((void**)&qkv,  g_qkv);
    cudaGetSymbolAddress((void**)&attn, g_attn);
    cudaGetSymbolAddress((void**)&qb,   g_q);
    cudaGetSymbolAddress((void**)&ck,   g_ck);
    cudaGetSymbolAddress((void**)&cv,   g_cv);
    cudaGetSymbolAddress((void**)&h1,   g_h1);
    cudaGetSymbolAddress((void**)&gg,   g_gg);
    cudaGetSymbolAddress((void**)&w1t,  g_w1t);
    cudaGetSymbolAddress((void**)&w2t,  g_w2t);

    cudaFuncSetAttribute(fattn_kernel, cudaFuncAttributeMaxDynamicSharedMemorySize, SMEM_ATTN);

    transpose_w<<<(CCH * CCH + 255) / 256, 256>>>(conv1_w, w1t);
    transpose_w<<<(CCH * CCH + 255) / 256, 256>>>(co_w,    w2t);

    gn_kernel<<<dim3(32, NB), 256>>>(x, gn_s, gn_b, gnt);

    gemm_kernel<<<dim3(CCH/64, MTOT/128), 256>>>(gnt, w1t, conv1_b, nullptr, xseq,
                                                 MTOT, CCH, CCH, 0);

    // ---- self-attention ----
    ln_kernel<<<MTOT, 256>>>(xseq, ln1_s, ln1_b, t);
    gemm_kernel<<<dim3(C3/64, MTOT/128), 256>>>(t, sa_in_w, nullptr, nullptr, qkv,
                                                MTOT, C3, CCH, 0);
    fattn_kernel<<<dim3(HW/QT, NH, NB), 256, SMEM_ATTN>>>(
        qkv, qkv + CCH, qkv + 2 * CCH, attn,
        HW, C3, C3, C3, CCH,
        (long long)HW * C3, (long long)HW * C3,
        (long long)HW * C3, (long long)HW * CCH);
    gemm_kernel<<<dim3(CCH/64, MTOT/128), 256>>>(attn, sa_out_w, sa_out_b, xseq, xseq,
                                                 MTOT, CCH, CCH, 0);

    // ---- cross-attention ----
    ln_kernel<<<MTOT, 256>>>(xseq, ln2_s, ln2_b, t);
    gemm_kernel<<<dim3(CCH/64, MTOT/128), 256>>>(t, ca_q_w, nullptr, nullptr, qb,
                                                 MTOT, CCH, CCH, 0);
    gemm_kernel<<<dim3(CCH/64, (NB*CTXL + 127)/128), 256>>>(context, ca_k_w, nullptr, nullptr, ck,
                                                            NB * CTXL, CCH, DCTX, 0);
    gemm_kernel<<<dim3(CCH/64, (NB*CTXL + 127)/128), 256>>>(context, ca_v_w, nullptr, nullptr, cv,
                                                            NB * CTXL, CCH, DCTX, 0);
    fattn_kernel<<<dim3(HW/QT, NH, NB), 256, SMEM_ATTN>>>(
        qb, ck, cv, attn,
        CTXL, CCH, CCH, CCH, CCH,
        (long long)HW * CCH, (long long)CTXL * CCH,
        (long long)CTXL * CCH, (long long)HW * CCH);
    gemm_kernel<<<dim3(CCH/64, MTOT/128), 256>>>(attn, ca_out_w, ca_out_b, xseq, xseq,
                                                 MTOT, CCH, CCH, 0);

    // ---- GeGLU FFN ----
    ln_kernel<<<MTOT, 256>>>(xseq, ln3_s, ln3_b, t);
    gemm_kernel<<<dim3(F8/64, MTOT/128), 256>>>(t, lin1_w, lin1_b, nullptr, h1,
                                                MTOT, F8, CCH, 0);
    geglu_kernel<<<(unsigned)(((size_t)MTOT * F4 + 255) / 256), 256>>>(h1, gg);
    gemm_kernel<<<dim3(CCH/64, MTOT/128), 256>>>(gg, lin2_w, lin2_b, xseq, xseq,
                                                 MTOT, CCH, F4, 0);

    // ---- output conv + long residual ----
    gemm_kernel<<<dim3(CCH/64, MTOT/128), 256>>>(xseq, w2t, co_b, x, out,
                                                 MTOT, CCH, CCH, 1);
}

// round 5
// speedup vs baseline: 7.6639x; 1.6501x over previous
#include <cuda_runtime.h>
#include <math.h>
#include <stdint.h>

#define NB   8
#define CCH  640
#define HW   1024
#define C3   1920
#define NH   8
#define DH   80
#define CTXL 77
#define DCTX 512
#define F8   5120
#define F4   2560
#define MTOT (NB*HW)   // 8192

// attention tiling
#define QT 64
#define KT 64
#define QP 81
#define PP 65
#define SMEM_ATTN ((3*QT*QP + QT*PP)*4)

// -------- scratch --------
__device__ float g_gnt [NB*HW*CCH];
__device__ float g_xseq[NB*HW*CCH];
__device__ float g_t   [NB*HW*CCH];
__device__ float g_qkv [NB*HW*C3];
__device__ float g_attn[NB*HW*CCH];
__device__ float g_q   [NB*HW*CCH];
__device__ float g_ck  [NB*CTXL*CCH];
__device__ float g_cv  [NB*CTXL*CCH];
__device__ float g_h1  [NB*HW*F8];
__device__ float g_gg  [NB*HW*F4];
__device__ float g_w1t [CCH*CCH];
__device__ float g_w2t [CCH*CCH];

__global__ void transpose_w(const float* __restrict__ w, float* __restrict__ wt) {
    int idx = blockIdx.x * blockDim.x + threadIdx.x;
    if (idx < CCH * CCH) {
        int o = idx / CCH, c = idx % CCH;
        wt[c * CCH + o] = w[idx];
    }
}

// -------- GroupNorm --------
__global__ __launch_bounds__(256) void gn_kernel(
    const float* __restrict__ x, const float* __restrict__ s,
    const float* __restrict__ b, float* __restrict__ out)
{
    const int g = blockIdx.x;
    const int n = blockIdx.y;
    const int cpg = CCH / 32;
    const int cnt = cpg * HW;
    const float* xp = x + ((size_t)n * CCH + (size_t)g * cpg) * HW;

    float sum = 0.f, sq = 0.f;
    for (int i = threadIdx.x; i < cnt; i += 256) {
        float v = xp[i]; sum += v; sq += v * v;
    }
    __shared__ float ss[8], sv[8];
    int lane = threadIdx.x & 31, wid = threadIdx.x >> 5;
    #pragma unroll
    for (int o = 16; o > 0; o >>= 1) {
        sum += __shfl_xor_sync(0xffffffffu, sum, o);
        sq  += __shfl_xor_sync(0xffffffffu, sq,  o);
    }
    if (lane == 0) { ss[wid] = sum; sv[wid] = sq; }
    __syncthreads();
    if (threadIdx.x == 0) {
        float ts = 0.f, tq = 0.f;
        #pragma unroll
        for (int w = 0; w < 8; w++) { ts += ss[w]; tq += sv[w]; }
        ss[0] = ts; sv[0] = tq;
    }
    __syncthreads();
    float mu  = ss[0] / (float)cnt;
    float var = sv[0] / (float)cnt - mu * mu;
    float inv = rsqrtf(var + 1e-6f);

    for (int i = threadIdx.x; i < cnt; i += 256) {
        int cl = i >> 10, p = i & 1023;
        int c  = g * cpg + cl;
        float v = (xp[i] - mu) * inv * s[c] + b[c];
        out[((size_t)n * HW + p) * CCH + c] = v;
    }
}

// -------- LayerNorm --------
__global__ __launch_bounds__(256) void ln_kernel(
    const float* __restrict__ x, const float* __restrict__ s,
    const float* __restrict__ b, float* __restrict__ out)
{
    const size_t row = blockIdx.x;
    const float* xp = x + row * CCH;
    float sum = 0.f, sq = 0.f;
    for (int i = threadIdx.x; i < CCH; i += 256) {
        float v = xp[i]; sum += v; sq += v * v;
    }
    __shared__ float ss[8], sv[8];
    int lane = threadIdx.x & 31, wid = threadIdx.x >> 5;
    #pragma unroll
    for (int o = 16; o > 0; o >>= 1) {
        sum += __shfl_xor_sync(0xffffffffu, sum, o);
        sq  += __shfl_xor_sync(0xffffffffu, sq,  o);
    }
    if (lane == 0) { ss[wid] = sum; sv[wid] = sq; }
    __syncthreads();
    if (threadIdx.x == 0) {
        float ts = 0.f, tq = 0.f;
        #pragma unroll
        for (int w = 0; w < 8; w++) { ts += ss[w]; tq += sv[w]; }
        ss[0] = ts; sv[0] = tq;
    }
    __syncthreads();
    float mu  = ss[0] / (float)CCH;
    float var = sv[0] / (float)CCH - mu * mu;
    float inv = rsqrtf(var + 1e-5f);
    for (int i = threadIdx.x; i < CCH; i += 256)
        out[row * CCH + i] = (xp[i] - mu) * inv * s[i] + b[i];
}

// -------- TF32 tensor-core GEMM --------
// C[M,N] = A[M,K] @ B[K,N] (+bias) (+R). K%16==0, N%128==0.
// 128x128 tile, 8 warps each 64x32 via mma.m16n8k8.tf32, fp32 accum.
__device__ __forceinline__ uint32_t f2tf(float f) {
    uint32_t u;
    asm("cvt.rna.tf32.f32 %0, %1;" : "=r"(u) : "f"(f));
    return u;
}

__global__ __launch_bounds__(256) void gemm_tf32(
    const float* __restrict__ A, const float* __restrict__ B,
    const float* __restrict__ bias, const float* __restrict__ R,
    float* __restrict__ Cout, int M, int N, int K, int out_trans)
{
    // As: [stage][kchunk(2)][m(128)][pitch 12, k 0..7]  (12m+k distinct mod 32)
    // Bs: [stage][k(16)][pitch 136, n 0..127]           (8k+n  distinct mod 32)
    __shared__ uint32_t As[2][2][128][12];
    __shared__ uint32_t Bs[2][16][136];

    const int tid  = threadIdx.x;
    const int wid  = tid >> 5, lane = tid & 31;
    const int g    = lane >> 2, tg = lane & 3;
    const int wm   = (wid >> 2) * 64;
    const int wn   = (wid & 3) * 32;
    const int m0   = blockIdx.y * 128, n0 = blockIdx.x * 128;

    // staging map
    const int am = tid >> 1;            // 0..127
    const int ac = tid & 1;             // k-chunk
    const int bk = tid >> 4;            // 0..15
    const int bn = (tid & 15) * 8;      // 0..120

    float acc[4][4][4];
    #pragma unroll
    for (int i = 0; i < 4; i++)
        #pragma unroll
        for (int j = 0; j < 4; j++)
            #pragma unroll
            for (int c = 0; c < 4; c++) acc[i][j][c] = 0.f;

    auto do_stage = [&](int s, int k0) {
        int mg = m0 + am;
        float4 v0 = make_float4(0.f,0.f,0.f,0.f), v1 = v0;
        if (mg < M) {
            const float* ap = &A[(size_t)mg * K + k0 + ac * 8];
            v0 = *(const float4*)ap;
            v1 = *(const float4*)(ap + 4);
        }
        uint32_t* ad = &As[s][ac][am][0];
        ad[0] = f2tf(v0.x); ad[1] = f2tf(v0.y); ad[2] = f2tf(v0.z); ad[3] = f2tf(v0.w);
        ad[4] = f2tf(v1.x); ad[5] = f2tf(v1.y); ad[6] = f2tf(v1.z); ad[7] = f2tf(v1.w);

        const float* bp = &B[(size_t)(k0 + bk) * N + n0 + bn];
        float4 w0 = *(const float4*)bp;
        float4 w1 = *(const float4*)(bp + 4);
        uint32_t* bd = &Bs[s][bk][bn];
        bd[0] = f2tf(w0.x); bd[1] = f2tf(w0.y); bd[2] = f2tf(w0.z); bd[3] = f2tf(w0.w);
        bd[4] = f2tf(w1.x); bd[5] = f2tf(w1.y); bd[6] = f2tf(w1.z); bd[7] = f2tf(w1.w);
    };

    const int nst = K >> 4;
    do_stage(0, 0);
    __syncthreads();

    for (int t = 0; t < nst; t++) {
        const int cur = t & 1;
        if (t + 1 < nst) do_stage(cur ^ 1, (t + 1) << 4);

        #pragma unroll
        for (int c = 0; c < 2; c++) {
            uint32_t bf[4][2];
            #pragma unroll
            for (int nj = 0; nj < 4; nj++) {
                bf[nj][0] = Bs[cur][c*8 + tg    ][wn + nj*8 + g];
                bf[nj][1] = Bs[cur][c*8 + tg + 4][wn + nj*8 + g];
            }
            #pragma unroll
            for (int mi = 0; mi < 4; mi++) {
                uint32_t a0 = As[cur][c][wm + mi*16 + g    ][tg    ];
                uint32_t a1 = As[cur][c][wm + mi*16 + g + 8][tg    ];
                uint32_t a2 = As[cur][c][wm + mi*16 + g    ][tg + 4];
                uint32_t a3 = As[cur][c][wm + mi*16 + g + 8][tg + 4];
                #pragma unroll
                for (int nj = 0; nj < 4; nj++) {
                    asm volatile(
                        "mma.sync.aligned.m16n8k8.row.col.f32.tf32.tf32.f32 "
                        "{%0,%1,%2,%3}, {%4,%5,%6,%7}, {%8,%9}, {%0,%1,%2,%3};"
                        : "+f"(acc[mi][nj][0]), "+f"(acc[mi][nj][1]),
                          "+f"(acc[mi][nj][2]), "+f"(acc[mi][nj][3])
                        : "r"(a0), "r"(a1), "r"(a2), "r"(a3),
                          "r"(bf[nj][0]), "r"(bf[nj][1]));
                }
            }
        }
        __syncthreads();
    }

    // epilogue: c0:(g, tg*2) c1:(g, tg*2+1) c2:(g+8, tg*2) c3:(g+8, tg*2+1)
    #pragma unroll
    for (int mi = 0; mi < 4; mi++) {
        #pragma unroll
        for (int r = 0; r < 2; r++) {
            int m = m0 + wm + mi*16 + g + r*8;
            if (m >= M) continue;
            #pragma unroll
            for (int nj = 0; nj < 4; nj++) {
                int n = n0 + wn + nj*8 + tg*2;
                float v0 = acc[mi][nj][r*2 + 0];
                float v1 = acc[mi][nj][r*2 + 1];
                if (bias) { v0 += bias[n]; v1 += bias[n+1]; }
                size_t i0, i1;
                if (out_trans) {
                    int nb = m >> 10, p = m & 1023;
                    i0 = ((size_t)nb * N + n) * 1024 + p;
                    i1 = i0 + 1024;
                } else {
                    i0 = (size_t)m * N + n;
                    i1 = i0 + 1;
                }
                if (R) { v0 += R[i0]; v1 += R[i1]; }
                Cout[i0] = v0;
                Cout[i1] = v1;
            }
        }
    }
}

// -------- flash-style tiled attention (fp32) --------
__global__ __launch_bounds__(256) void fattn_kernel(
    const float* __restrict__ Q, const float* __restrict__ K,
    const float* __restrict__ V, float* __restrict__ O,
    int seq_kv, int qs, int ks, int vs, int os,
    long long qbs, long long kbs, long long vbs, long long obs)
{
    extern __shared__ float sm[];
    float* Qs = sm;
    float* Ks = Qs + QT*QP;
    float* Vs = Ks + KT*QP;
    float* Ps = Vs + KT*QP;

    const int qt = blockIdx.x, h = blockIdx.y, b = blockIdx.z;
    const int tid = threadIdx.x;
    const int ty = tid >> 4, tx = tid & 15;

    const float* qp = Q + (size_t)b * qbs + (size_t)h * DH;
    const float* kp = K + (size_t)b * kbs + (size_t)h * DH;
    const float* vp = V + (size_t)b * vbs + (size_t)h * DH;
    float*       op = O + (size_t)b * obs + (size_t)h * DH;

    for (int i = tid; i < QT*DH; i += 256) {
        int r = i / DH, d = i - r*DH;
        Qs[r*QP + d] = qp[(size_t)(qt*QT + r) * qs + d];
    }

    float m[4], l[4], o[4][5];
    #pragma unroll
    for (int i = 0; i < 4; i++) {
        m[i] = -1e30f; l[i] = 0.f;
        #pragma unroll
        for (int j = 0; j < 5; j++) o[i][j] = 0.f;
    }

    const float scale = 0.11180339887498949f;
    const int ntile = (seq_kv + KT - 1) / KT;

    for (int t = 0; t < ntile; t++) {
        const int k0 = t * KT;
        __syncthreads();
        for (int i = tid; i < KT*DH; i += 256) {
            int r = i / DH, d = i - r*DH;
            int kg = k0 + r;
            float kv = 0.f, vv = 0.f;
            if (kg < seq_kv) {
                kv = kp[(size_t)kg * ks + d];
                vv = vp[(size_t)kg * vs + d];
            }
            Ks[r*QP + d] = kv;
            Vs[r*QP + d] = vv;
        }
        __syncthreads();

        float s[4][4] = {};
        for (int d = 0; d < DH; d++) {
            float qv[4], kv[4];
            #pragma unroll
            for (int i = 0; i < 4; i++) qv[i] = Qs[(ty*4+i)*QP + d];
            #pragma unroll
            for (int j = 0; j < 4; j++) kv[j] = Ks[(tx*4+j)*QP + d];
            #pragma unroll
            for (int i = 0; i < 4; i++)
                #pragma unroll
                for (int j = 0; j < 4; j++)
                    s[i][j] += qv[i] * kv[j];
        }
        #pragma unroll
        for (int i = 0; i < 4; i++)
            #pragma unroll
            for (int j = 0; j < 4; j++) {
                s[i][j] *= scale;
                if (k0 + tx*4 + j >= seq_kv) s[i][j] = -1e30f;
            }

        #pragma unroll
        for (int i = 0; i < 4; i++) {
            float mt = fmaxf(fmaxf(s[i][0], s[i][1]), fmaxf(s[i][2], s[i][3]));
            #pragma unroll
            for (int off = 8; off > 0; off >>= 1)
                mt = fmaxf(mt, __shfl_xor_sync(0xffffffffu, mt, off));
            float mn = fmaxf(m[i], mt);
            float f  = __expf(m[i] - mn);
            m[i] = mn;
            float rs = 0.f;
            #pragma unroll
            for (int j = 0; j < 4; j++) {
                float p = __expf(s[i][j] - mn);
                s[i][j] = p;
                rs += p;
            }
            #pragma unroll
            for (int off = 8; off > 0; off >>= 1)
                rs += __shfl_xor_sync(0xffffffffu, rs, off);
            l[i] = l[i] * f + rs;
            #pragma unroll
            for (int j = 0; j < 5; j++) o[i][j] *= f;
        }

        #pragma unroll
        for (int i = 0; i < 4; i++)
            #pragma unroll
            for (int j = 0; j < 4; j++)
                Ps[(ty*4+i)*PP + tx*4+j] = s[i][j];
        __syncthreads();

        for (int k = 0; k < KT; k++) {
            float pv[4], vv[5];
            #pragma unroll
            for (int i = 0; i < 4; i++) pv[i] = Ps[(ty*4+i)*PP + k];
            #pragma unroll
            for (int j = 0; j < 5; j++) vv[j] = Vs[k*QP + tx*5+j];
            #pragma unroll
            for (int i = 0; i < 4; i++)
                #pragma unroll
                for (int j = 0; j < 5; j++)
                    o[i][j] += pv[i] * vv[j];
        }
    }

    #pragma unroll
    for (int i = 0; i < 4; i++) {
        float inv = 1.f / l[i];
        int qg = qt*QT + ty*4 + i;
        #pragma unroll
        for (int j = 0; j < 5; j++)
            op[(size_t)qg * os + tx*5 + j] = o[i][j] * inv;
    }
}

// -------- GeGLU --------
__global__ __launch_bounds__(256) void geglu_kernel(
    const float* __restrict__ h1, float* __restrict__ g)
{
    size_t i = (size_t)blockIdx.x * 256 + threadIdx.x;
    if (i < (size_t)MTOT * F4) {
        size_t row = i / F4, j = i % F4;
        float a  = h1[row * F8 + j];
        float x  = h1[row * F8 + F4 + j];
        float ge = 0.5f * x * (1.0f + erff(x * 0.70710678118654752f));
        g[i] = a * ge;
    }
}

extern "C" void kernel_launch(void* const* d_in, const int* in_sizes, int n_in,
                              void* d_out, int out_size)
{
    const float* x       = (const float*)d_in[0];
    const float* context = (const float*)d_in[1];
    const float* gn_s    = (const float*)d_in[2];
    const float* gn_b    = (const float*)d_in[3];
    const float* conv1_w = (const float*)d_in[4];
    const float* conv1_b = (const float*)d_in[5];
    const float* ln1_s   = (const float*)d_in[6];
    const float* ln1_b   = (const float*)d_in[7];
    const float* sa_in_w = (const float*)d_in[8];
    const float* sa_out_w= (const float*)d_in[9];
    const float* sa_out_b= (const float*)d_in[10];
    const float* ln2_s   = (const float*)d_in[11];
    const float* ln2_b   = (const float*)d_in[12];
    const float* ca_q_w  = (const float*)d_in[13];
    const float* ca_k_w  = (const float*)d_in[14];
    const float* ca_v_w  = (const float*)d_in[15];
    const float* ca_out_w= (const float*)d_in[16];
    const float* ca_out_b= (const float*)d_in[17];
    const float* ln3_s   = (const float*)d_in[18];
    const float* ln3_b   = (const float*)d_in[19];
    const float* lin1_w  = (const float*)d_in[20];
    const float* lin1_b  = (const float*)d_in[21];
    const float* lin2_w  = (const float*)d_in[22];
    const float* lin2_b  = (const float*)d_in[23];
    const float* co_w    = (const float*)d_in[24];
    const float* co_b    = (const float*)d_in[25];
    float* out = (float*)d_out;

    float *gnt, *xseq, *t, *qkv, *attn, *qb, *ck, *cv, *h1, *gg, *w1t, *w2t;
    cudaGetSymbolAddress((void**)&gnt,  g_gnt);
    cudaGetSymbolAddress((void**)&xseq, g_xseq);
    cudaGetSymbolAddress((void**)&t,    g_t);
    cudaGetSymbolAddress((void**)&qkv,  g_qkv);
    cudaGetSymbolAddress((void**)&attn, g_attn);
    cudaGetSymbolAddress((void**)&qb,   g_q);
    cudaGetSymbolAddress((void**)&ck,   g_ck);
    cudaGetSymbolAddress((void**)&cv,   g_cv);
    cudaGetSymbolAddress((void**)&h1,   g_h1);
    cudaGetSymbolAddress((void**)&gg,   g_gg);
    cudaGetSymbolAddress((void**)&w1t,  g_w1t);
    cudaGetSymbolAddress((void**)&w2t,  g_w2t);

    cudaFuncSetAttribute(fattn_kernel, cudaFuncAttributeMaxDynamicSharedMemorySize, SMEM_ATTN);

    transpose_w<<<(CCH * CCH + 255) / 256, 256>>>(conv1_w, w1t);
    transpose_w<<<(CCH * CCH + 255) / 256, 256>>>(co_w,    w2t);

    gn_kernel<<<dim3(32, NB), 256>>>(x, gn_s, gn_b, gnt);

    gemm_tf32<<<dim3(CCH/128, MTOT/128), 256>>>(gnt, w1t, conv1_b, nullptr, xseq,
                                                MTOT, CCH, CCH, 0);

    // ---- self-attention ----
    ln_kernel<<<MTOT, 256>>>(xseq, ln1_s, ln1_b, t);
    gemm_tf32<<<dim3(C3/128, MTOT/128), 256>>>(t, sa_in_w, nullptr, nullptr, qkv,
                                               MTOT, C3, CCH, 0);
    fattn_kernel<<<dim3(HW/QT, NH, NB), 256, SMEM_ATTN>>>(
        qkv, qkv + CCH, qkv + 2 * CCH, attn,
        HW, C3, C3, C3, CCH,
        (long long)HW * C3, (long long)HW * C3,
        (long long)HW * C3, (long long)HW * CCH);
    gemm_tf32<<<dim3(CCH/128, MTOT/128), 256>>>(attn, sa_out_w, sa_out_b, xseq, xseq,
                                                MTOT, CCH, CCH, 0);

    // ---- cross-attention ----
    ln_kernel<<<MTOT, 256>>>(xseq, ln2_s, ln2_b, t);
    gemm_tf32<<<dim3(CCH/128, MTOT/128), 256>>>(t, ca_q_w, nullptr, nullptr, qb,
                                                MTOT, CCH, CCH, 0);
    gemm_tf32<<<dim3(CCH/128, (NB*CTXL + 127)/128), 256>>>(context, ca_k_w, nullptr, nullptr, ck,
                                                           NB * CTXL, CCH, DCTX, 0);
    gemm_tf32<<<dim3(CCH/128, (NB*CTXL + 127)/128), 256>>>(context, ca_v_w, nullptr, nullptr, cv,
                                                           NB * CTXL, CCH, DCTX, 0);
    fattn_kernel<<<dim3(HW/QT, NH, NB), 256, SMEM_ATTN>>>(
        qb, ck, cv, attn,
        CTXL, CCH, CCH, CCH, CCH,
        (long long)HW * CCH, (long long)CTXL * CCH,
        (long long)CTXL * CCH, (long long)HW * CCH);
    gemm_tf32<<<dim3(CCH/128, MTOT/128), 256>>>(attn, ca_out_w, ca_out_b, xseq, xseq,
                                                MTOT, CCH, CCH, 0);

    // ---- GeGLU FFN ----
    ln_kernel<<<MTOT, 256>>>(xseq, ln3_s, ln3_b, t);
    gemm_tf32<<<dim3(F8/128, MTOT/128), 256>>>(t, lin1_w, lin1_b, nullptr, h1,
                                               MTOT, F8, CCH, 0);
    geglu_kernel<<<(unsigned)(((size_t)MTOT * F4 + 255) / 256), 256>>>(h1, gg);
    gemm_tf32<<<dim3(CCH/128, MTOT/128), 256>>>(gg, lin2_w, lin2_b, xseq, xseq,
                                                MTOT, CCH, F4, 0);

    // ---- output conv + long residual ----
    gemm_tf32<<<dim3(CCH/128, MTOT/128), 256>>>(xseq, w2t, co_b, x, out,
                                                MTOT, CCH, CCH, 1);
}

// round 7
// speedup vs baseline: 8.8711x; 1.1575x over previous
#include <cuda_runtime.h>
#include <math.h>
#include <stdint.h>

#define NB   8
#define CCH  640
#define HW   1024
#define C3   1920
#define NH   8
#define DH   80
#define CTXL 77
#define DCTX 512
#define F8   5120
#define F4   2560
#define MTOT (NB*HW)   // 8192

// attention tiling
#define QT 64
#define KT 64
#define QP 81
#define PP 65
#define SMEM_ATTN ((3*QT*QP + QT*PP)*4)

// GEMM pipeline
#define STAGES 3
#define AP 20                      // A smem pitch (floats): 20g+tg distinct mod 32
#define BP 136                     // B smem pitch (floats): 8tg+g distinct mod 32
#define A_STG (128*AP)             // floats per A stage
#define B_STG (16*BP)              // floats per B stage
#define SMEM_GEMM ((STAGES*(A_STG + B_STG))*4)

// -------- scratch --------
__device__ float g_gnt [NB*HW*CCH];
__device__ float g_xseq[NB*HW*CCH];
__device__ float g_t   [NB*HW*CCH];
__device__ float g_qkv [NB*HW*C3];
__device__ float g_attn[NB*HW*CCH];
__device__ float g_q   [NB*HW*CCH];
__device__ float g_ck  [NB*CTXL*CCH];
__device__ float g_cv  [NB*CTXL*CCH];
__device__ float g_h1  [NB*HW*F8];
__device__ float g_gg  [NB*HW*F4];
__device__ float g_w1t [CCH*CCH];
__device__ float g_w2t [CCH*CCH];

__global__ void transpose_w(const float* __restrict__ w, float* __restrict__ wt) {
    int idx = blockIdx.x * blockDim.x + threadIdx.x;
    if (idx < CCH * CCH) {
        int o = idx / CCH, c = idx % CCH;
        wt[c * CCH + o] = w[idx];
    }
}

// -------- GroupNorm --------
__global__ __launch_bounds__(256) void gn_kernel(
    const float* __restrict__ x, const float* __restrict__ s,
    const float* __restrict__ b, float* __restrict__ out)
{
    const int g = blockIdx.x;
    const int n = blockIdx.y;
    const int cpg = CCH / 32;
    const int cnt = cpg * HW;
    const float* xp = x + ((size_t)n * CCH + (size_t)g * cpg) * HW;

    float sum = 0.f, sq = 0.f;
    for (int i = threadIdx.x; i < cnt; i += 256) {
        float v = xp[i]; sum += v; sq += v * v;
    }
    __shared__ float ss[8], sv[8];
    int lane = threadIdx.x & 31, wid = threadIdx.x >> 5;
    #pragma unroll
    for (int o = 16; o > 0; o >>= 1) {
        sum += __shfl_xor_sync(0xffffffffu, sum, o);
        sq  += __shfl_xor_sync(0xffffffffu, sq,  o);
    }
    if (lane == 0) { ss[wid] = sum; sv[wid] = sq; }
    __syncthreads();
    if (threadIdx.x == 0) {
        float ts = 0.f, tq = 0.f;
        #pragma unroll
        for (int w = 0; w < 8; w++) { ts += ss[w]; tq += sv[w]; }
        ss[0] = ts; sv[0] = tq;
    }
    __syncthreads();
    float mu  = ss[0] / (float)cnt;
    float var = sv[0] / (float)cnt - mu * mu;
    float inv = rsqrtf(var + 1e-6f);

    for (int i = threadIdx.x; i < cnt; i += 256) {
        int cl = i >> 10, p = i & 1023;
        int c  = g * cpg + cl;
        float v = (xp[i] - mu) * inv * s[c] + b[c];
        out[((size_t)n * HW + p) * CCH + c] = v;
    }
}

// -------- LayerNorm --------
__global__ __launch_bounds__(256) void ln_kernel(
    const float* __restrict__ x, const float* __restrict__ s,
    const float* __restrict__ b, float* __restrict__ out)
{
    const size_t row = blockIdx.x;
    const float* xp = x + row * CCH;
    float sum = 0.f, sq = 0.f;
    for (int i = threadIdx.x; i < CCH; i += 256) {
        float v = xp[i]; sum += v; sq += v * v;
    }
    __shared__ float ss[8], sv[8];
    int lane = threadIdx.x & 31, wid = threadIdx.x >> 5;
    #pragma unroll
    for (int o = 16; o > 0; o >>= 1) {
        sum += __shfl_xor_sync(0xffffffffu, sum, o);
        sq  += __shfl_xor_sync(0xffffffffu, sq,  o);
    }
    if (lane == 0) { ss[wid] = sum; sv[wid] = sq; }
    __syncthreads();
    if (threadIdx.x == 0) {
        float ts = 0.f, tq = 0.f;
        #pragma unroll
        for (int w = 0; w < 8; w++) { ts += ss[w]; tq += sv[w]; }
        ss[0] = ts; sv[0] = tq;
    }
    __syncthreads();
    float mu  = ss[0] / (float)CCH;
    float var = sv[0] / (float)CCH - mu * mu;
    float inv = rsqrtf(var + 1e-5f);
    for (int i = threadIdx.x; i < CCH; i += 256)
        out[row * CCH + i] = (xp[i] - mu) * inv * s[i] + b[i];
}

// -------- TF32 tensor-core GEMM with cp.async 3-stage pipeline --------
__device__ __forceinline__ uint32_t f2tf(float f) {
    uint32_t u;
    asm("cvt.rna.tf32.f32 %0, %1;" : "=r"(u) : "f"(f));
    return u;
}
__device__ __forceinline__ void cpa16(float* smem, const float* g, int sz) {
    uint32_t s = (uint32_t)__cvta_generic_to_shared(smem);
    asm volatile("cp.async.cg.shared.global [%0], [%1], 16, %2;" :: "r"(s), "l"(g), "r"(sz));
}
__device__ __forceinline__ void cpa_commit() {
    asm volatile("cp.async.commit_group;");
}

__global__ __launch_bounds__(256) void gemm_tf32(
    const float* __restrict__ A, const float* __restrict__ B,
    const float* __restrict__ bias, const float* __restrict__ R,
    float* __restrict__ Cout, int M, int N, int K, int out_trans)
{
    extern __shared__ float sm[];
    float* As = sm;                       // [STAGES][128][AP]
    float* Bs = sm + STAGES * A_STG;      // [STAGES][16][BP]

    const int tid  = threadIdx.x;
    const int wid  = tid >> 5, lane = tid & 31;
    const int g    = lane >> 2, tg = lane & 3;
    const int wm   = (wid >> 2) * 64;
    const int wn   = (wid & 3) * 32;
    const int m0   = blockIdx.y * 128, n0 = blockIdx.x * 128;

    // staging maps
    const int arow = tid >> 1;            // 0..127
    const int acol = (tid & 1) * 8;       // 0 or 8
    const int brow = tid >> 4;            // 0..15
    const int bcol = (tid & 15) * 8;      // 0..120

    const int a_ok   = (m0 + arow < M) ? 16 : 0;
    const int a_row_safe = (m0 + arow < M) ? (m0 + arow) : 0;

    float acc[4][4][4];
    #pragma unroll
    for (int i = 0; i < 4; i++)
        #pragma unroll
        for (int j = 0; j < 4; j++)
            #pragma unroll
            for (int c = 0; c < 4; c++) acc[i][j][c] = 0.f;

    auto issue = [&](int slot, int kt) {
        const int k0 = kt << 4;
        const float* ag = &A[(size_t)a_row_safe * K + k0 + acol];
        float* ad = &As[slot * A_STG + arow * AP + acol];
        cpa16(ad,     ag,     a_ok);
        cpa16(ad + 4, ag + 4, a_ok);
        const float* bg = &B[(size_t)(k0 + brow) * N + n0 + bcol];
        float* bd = &Bs[slot * B_STG + brow * BP + bcol];
        cpa16(bd,     bg,     16);
        cpa16(bd + 4, bg + 4, 16);
    };

    const int nst = K >> 4;
    issue(0, 0); cpa_commit();
    issue(1, 1); cpa_commit();

    int slot = 0;
    for (int t = 0; t < nst; t++) {
        asm volatile("cp.async.wait_group 1;");
        __syncthreads();

        const int nt = t + STAGES - 1;
        if (nt < nst) {
            int ns = slot + 2; if (ns >= STAGES) ns -= STAGES;
            issue(ns, nt);
        }
        cpa_commit();

        const float* Ac = &As[slot * A_STG];
        const float* Bc = &Bs[slot * B_STG];
        #pragma unroll
        for (int c = 0; c < 2; c++) {
            uint32_t bf[4][2];
            #pragma unroll
            for (int nj = 0; nj < 4; nj++) {
                bf[nj][0] = f2tf(Bc[(c*8 + tg    ) * BP + wn + nj*8 + g]);
                bf[nj][1] = f2tf(Bc[(c*8 + tg + 4) * BP + wn + nj*8 + g]);
            }
            #pragma unroll
            for (int mi = 0; mi < 4; mi++) {
                uint32_t a0 = f2tf(Ac[(wm + mi*16 + g    ) * AP + c*8 + tg    ]);
                uint32_t a1 = f2tf(Ac[(wm + mi*16 + g + 8) * AP + c*8 + tg    ]);
                uint32_t a2 = f2tf(Ac[(wm + mi*16 + g    ) * AP + c*8 + tg + 4]);
                uint32_t a3 = f2tf(Ac[(wm + mi*16 + g + 8) * AP + c*8 + tg + 4]);
                #pragma unroll
                for (int nj = 0; nj < 4; nj++) {
                    asm volatile(
                        "mma.sync.aligned.m16n8k8.row.col.f32.tf32.tf32.f32 "
                        "{%0,%1,%2,%3}, {%4,%5,%6,%7}, {%8,%9}, {%0,%1,%2,%3};"
                        : "+f"(acc[mi][nj][0]), "+f"(acc[mi][nj][1]),
                          "+f"(acc[mi][nj][2]), "+f"(acc[mi][nj][3])
                        : "r"(a0), "r"(a1), "r"(a2), "r"(a3),
                          "r"(bf[nj][0]), "r"(bf[nj][1]));
                }
            }
        }
        slot++; if (slot >= STAGES) slot = 0;
        __syncthreads();
    }

    // epilogue: c0:(g, tg*2) c1:(g, tg*2+1) c2:(g+8, tg*2) c3:(g+8, tg*2+1)
    #pragma unroll
    for (int mi = 0; mi < 4; mi++) {
        #pragma unroll
        for (int r = 0; r < 2; r++) {
            int m = m0 + wm + mi*16 + g + r*8;
            if (m >= M) continue;
            #pragma unroll
            for (int nj = 0; nj < 4; nj++) {
                int n = n0 + wn + nj*8 + tg*2;
                float v0 = acc[mi][nj][r*2 + 0];
                float v1 = acc[mi][nj][r*2 + 1];
                if (bias) { v0 += bias[n]; v1 += bias[n+1]; }
                size_t i0, i1;
                if (out_trans) {
                    int nb = m >> 10, p = m & 1023;
                    i0 = ((size_t)nb * N + n) * 1024 + p;
                    i1 = i0 + 1024;
                } else {
                    i0 = (size_t)m * N + n;
                    i1 = i0 + 1;
                }
                if (R) { v0 += R[i0]; v1 += R[i1]; }
                Cout[i0] = v0;
                Cout[i1] = v1;
            }
        }
    }
}

// -------- flash-style tiled attention (fp32) --------
__global__ __launch_bounds__(256) void fattn_kernel(
    const float* __restrict__ Q, const float* __restrict__ K,
    const float* __restrict__ V, float* __restrict__ O,
    int seq_kv, int qs, int ks, int vs, int os,
    long long qbs, long long kbs, long long vbs, long long obs)
{
    extern __shared__ float smf[];
    float* Qs = smf;
    float* Ks = Qs + QT*QP;
    float* Vs = Ks + KT*QP;
    float* Ps = Vs + KT*QP;

    const int qt = blockIdx.x, h = blockIdx.y, b = blockIdx.z;
    const int tid = threadIdx.x;
    const int ty = tid >> 4, tx = tid & 15;

    const float* qp = Q + (size_t)b * qbs + (size_t)h * DH;
    const float* kp = K + (size_t)b * kbs + (size_t)h * DH;
    const float* vp = V + (size_t)b * vbs + (size_t)h * DH;
    float*       op = O + (size_t)b * obs + (size_t)h * DH;

    for (int i = tid; i < QT*DH; i += 256) {
        int r = i / DH, d = i - r*DH;
        Qs[r*QP + d] = qp[(size_t)(qt*QT + r) * qs + d];
    }

    float m[4], l[4], o[4][5];
    #pragma unroll
    for (int i = 0; i < 4; i++) {
        m[i] = -1e30f; l[i] = 0.f;
        #pragma unroll
        for (int j = 0; j < 5; j++) o[i][j] = 0.f;
    }

    const float scale = 0.11180339887498949f;
    const int ntile = (seq_kv + KT - 1) / KT;

    for (int t = 0; t < ntile; t++) {
        const int k0 = t * KT;
        __syncthreads();
        for (int i = tid; i < KT*DH; i += 256) {
            int r = i / DH, d = i - r*DH;
            int kg = k0 + r;
            float kv = 0.f, vv = 0.f;
            if (kg < seq_kv) {
                kv = kp[(size_t)kg * ks + d];
                vv = vp[(size_t)kg * vs + d];
            }
            Ks[r*QP + d] = kv;
            Vs[r*QP + d] = vv;
        }
        __syncthreads();

        float s[4][4] = {};
        for (int d = 0; d < DH; d++) {
            float qv[4], kv[4];
            #pragma unroll
            for (int i = 0; i < 4; i++) qv[i] = Qs[(ty*4+i)*QP + d];
            #pragma unroll
            for (int j = 0; j < 4; j++) kv[j] = Ks[(tx*4+j)*QP + d];
            #pragma unroll
            for (int i = 0; i < 4; i++)
                #pragma unroll
                for (int j = 0; j < 4; j++)
                    s[i][j] += qv[i] * kv[j];
        }
        #pragma unroll
        for (int i = 0; i < 4; i++)
            #pragma unroll
            for (int j = 0; j < 4; j++) {
                s[i][j] *= scale;
                if (k0 + tx*4 + j >= seq_kv) s[i][j] = -1e30f;
            }

        #pragma unroll
        for (int i = 0; i < 4; i++) {
            float mt = fmaxf(fmaxf(s[i][0], s[i][1]), fmaxf(s[i][2], s[i][3]));
            #pragma unroll
            for (int off = 8; off > 0; off >>= 1)
                mt = fmaxf(mt, __shfl_xor_sync(0xffffffffu, mt, off));
            float mn = fmaxf(m[i], mt);
            float f  = __expf(m[i] - mn);
            m[i] = mn;
            float rs = 0.f;
            #pragma unroll
            for (int j = 0; j < 4; j++) {
                float p = __expf(s[i][j] - mn);
                s[i][j] = p;
                rs += p;
            }
            #pragma unroll
            for (int off = 8; off > 0; off >>= 1)
                rs += __shfl_xor_sync(0xffffffffu, rs, off);
            l[i] = l[i] * f + rs;
            #pragma unroll
            for (int j = 0; j < 5; j++) o[i][j] *= f;
        }

        #pragma unroll
        for (int i = 0; i < 4; i++)
            #pragma unroll
            for (int j = 0; j < 4; j++)
                Ps[(ty*4+i)*PP + tx*4+j] = s[i][j];
        __syncthreads();

        for (int k = 0; k < KT; k++) {
            float pv[4], vv[5];
            #pragma unroll
            for (int i = 0; i < 4; i++) pv[i] = Ps[(ty*4+i)*PP + k];
            #pragma unroll
            for (int j = 0; j < 5; j++) vv[j] = Vs[k*QP + tx*5+j];
            #pragma unroll
            for (int i = 0; i < 4; i++)
                #pragma unroll
                for (int j = 0; j < 5; j++)
                    o[i][j] += pv[i] * vv[j];
        }
    }

    #pragma unroll
    for (int i = 0; i < 4; i++) {
        float inv = 1.f / l[i];
        int qg = qt*QT + ty*4 + i;
        #pragma unroll
        for (int j = 0; j < 5; j++)
            op[(size_t)qg * os + tx*5 + j] = o[i][j] * inv;
    }
}

// -------- GeGLU --------
__global__ __launch_bounds__(256) void geglu_kernel(
    const float* __restrict__ h1, float* __restrict__ g)
{
    size_t i = (size_t)blockIdx.x * 256 + threadIdx.x;
    if (i < (size_t)MTOT * F4) {
        size_t row = i / F4, j = i % F4;
        float a  = h1[row * F8 + j];
        float x  = h1[row * F8 + F4 + j];
        float ge = 0.5f * x * (1.0f + erff(x * 0.70710678118654752f));
        g[i] = a * ge;
    }
}

extern "C" void kernel_launch(void* const* d_in, const int* in_sizes, int n_in,
                              void* d_out, int out_size)
{
    const float* x       = (const float*)d_in[0];
    const float* context = (const float*)d_in[1];
    const float* gn_s    = (const float*)d_in[2];
    const float* gn_b    = (const float*)d_in[3];
    const float* conv1_w = (const float*)d_in[4];
    const float* conv1_b = (const float*)d_in[5];
    const float* ln1_s   = (const float*)d_in[6];
    const float* ln1_b   = (const float*)d_in[7];
    const float* sa_in_w = (const float*)d_in[8];
    const float* sa_out_w= (const float*)d_in[9];
    const float* sa_out_b= (const float*)d_in[10];
    const float* ln2_s   = (const float*)d_in[11];
    const float* ln2_b   = (const float*)d_in[12];
    const float* ca_q_w  = (const float*)d_in[13];
    const float* ca_k_w  = (const float*)d_in[14];
    const float* ca_v_w  = (const float*)d_in[15];
    const float* ca_out_w= (const float*)d_in[16];
    const float* ca_out_b= (const float*)d_in[17];
    const float* ln3_s   = (const float*)d_in[18];
    const float* ln3_b   = (const float*)d_in[19];
    const float* lin1_w  = (const float*)d_in[20];
    const float* lin1_b  = (const float*)d_in[21];
    const float* lin2_w  = (const float*)d_in[22];
    const float* lin2_b  = (const float*)d_in[23];
    const float* co_w    = (const float*)d_in[24];
    const float* co_b    = (const float*)d_in[25];
    float* out = (float*)d_out;

    float *gnt, *xseq, *t, *qkv, *attn, *qb, *ck, *cv, *h1, *gg, *w1t, *w2t;
    cudaGetSymbolAddress((void**)&gnt,  g_gnt);
    cudaGetSymbolAddress((void**)&xseq, g_xseq);
    cudaGetSymbolAddress((void**)&t,    g_t);
    cudaGetSymbolAddress((void**)&qkv,  g_qkv);
    cudaGetSymbolAddress((void**)&attn, g_attn);
    cudaGetSymbolAddress((void**)&qb,   g_q);
    cudaGetSymbolAddress((void**)&ck,   g_ck);
    cudaGetSymbolAddress((void**)&cv,   g_cv);
    cudaGetSymbolAddress((void**)&h1,   g_h1);
    cudaGetSymbolAddress((void**)&gg,   g_gg);
    cudaGetSymbolAddress((void**)&w1t,  g_w1t);
    cudaGetSymbolAddress((void**)&w2t,  g_w2t);

    cudaFuncSetAttribute(fattn_kernel, cudaFuncAttributeMaxDynamicSharedMemorySize, SMEM_ATTN);
    cudaFuncSetAttribute(gemm_tf32,   cudaFuncAttributeMaxDynamicSharedMemorySize, SMEM_GEMM);

    transpose_w<<<(CCH * CCH + 255) / 256, 256>>>(conv1_w, w1t);
    transpose_w<<<(CCH * CCH + 255) / 256, 256>>>(co_w,    w2t);

    gn_kernel<<<dim3(32, NB), 256>>>(x, gn_s, gn_b, gnt);

    gemm_tf32<<<dim3(CCH/128, MTOT/128), 256, SMEM_GEMM>>>(gnt, w1t, conv1_b, nullptr, xseq,
                                                           MTOT, CCH, CCH, 0);

    // ---- self-attention ----
    ln_kernel<<<MTOT, 256>>>(xseq, ln1_s, ln1_b, t);
    gemm_tf32<<<dim3(C3/128, MTOT/128), 256, SMEM_GEMM>>>(t, sa_in_w, nullptr, nullptr, qkv,
                                                          MTOT, C3, CCH, 0);
    fattn_kernel<<<dim3(HW/QT, NH, NB), 256, SMEM_ATTN>>>(
        qkv, qkv + CCH, qkv + 2 * CCH, attn,
        HW, C3, C3, C3, CCH,
        (long long)HW * C3, (long long)HW * C3,
        (long long)HW * C3, (long long)HW * CCH);
    gemm_tf32<<<dim3(CCH/128, MTOT/128), 256, SMEM_GEMM>>>(attn, sa_out_w, sa_out_b, xseq, xseq,
                                                           MTOT, CCH, CCH, 0);

    // ---- cross-attention ----
    ln_kernel<<<MTOT, 256>>>(xseq, ln2_s, ln2_b, t);
    gemm_tf32<<<dim3(CCH/128, MTOT/128), 256, SMEM_GEMM>>>(t, ca_q_w, nullptr, nullptr, qb,
                                                           MTOT, CCH, CCH, 0);
    gemm_tf32<<<dim3(CCH/128, (NB*CTXL + 127)/128), 256, SMEM_GEMM>>>(context, ca_k_w, nullptr, nullptr, ck,
                                                                      NB * CTXL, CCH, DCTX, 0);
    gemm_tf32<<<dim3(CCH/128, (NB*CTXL + 127)/128), 256, SMEM_GEMM>>>(context, ca_v_w, nullptr, nullptr, cv,
                                                                      NB * CTXL, CCH, DCTX, 0);
    fattn_kernel<<<dim3(HW/QT, NH, NB), 256, SMEM_ATTN>>>(
        qb, ck, cv, attn,
        CTXL, CCH, CCH, CCH, CCH,
        (long long)HW * CCH, (long long)CTXL * CCH,
        (long long)CTXL * CCH, (long long)HW * CCH);
    gemm_tf32<<<dim3(CCH/128, MTOT/128), 256, SMEM_GEMM>>>(attn, ca_out_w, ca_out_b, xseq, xseq,
                                                           MTOT, CCH, CCH, 0);

    // ---- GeGLU FFN ----
    ln_kernel<<<MTOT, 256>>>(xseq, ln3_s, ln3_b, t);
    gemm_tf32<<<dim3(F8/128, MTOT/128), 256, SMEM_GEMM>>>(t, lin1_w, lin1_b, nullptr, h1,
                                                          MTOT, F8, CCH, 0);
    geglu_kernel<<<(unsigned)(((size_t)MTOT * F4 + 255) / 256), 256>>>(h1, gg);
    gemm_tf32<<<dim3(CCH/128, MTOT/128), 256, SMEM_GEMM>>>(gg, lin2_w, lin2_b, xseq, xseq,
                                                           MTOT, CCH, F4, 0);

    // ---- output conv + long residual ----
    gemm_tf32<<<dim3(CCH/128, MTOT/128), 256, SMEM_GEMM>>>(xseq, w2t, co_b, x, out,
                                                           MTOT, CCH, CCH, 1);
}

// round 10
// speedup vs baseline: 9.1270x; 1.0288x over previous
#include <cuda_runtime.h>
#include <math.h>
#include <stdint.h>

#define NB   8
#define CCH  640
#define HW   1024
#define C3   1920
#define NH   8
#define DH   80
#define CTXL 77
#define DCTX 512
#define F8   5120
#define F4   2560
#define MTOT (NB*HW)   // 8192
#define MCTX (NB*CTXL) // 616

// attention tiling
#define QT 64
#define KT 64
#define QP 81
#define PP 65
#define SMEM_ATTN ((3*QT*QP + QT*PP)*4)

// GEMM pipeline
#define STAGES 4
#define AP 20                      // A smem pitch (floats)
#define BP 136                     // B smem pitch (floats)
#define A_STG (128*AP)
#define B_STG (16*BP)
#define SMEM_GEMM ((STAGES*(A_STG + B_STG))*4)   // 75776 B

// -------- scratch --------
__device__ float g_gnt [MTOT*CCH];
__device__ float g_xseq[MTOT*CCH];
__device__ float g_t   [MTOT*CCH];
__device__ float g_qkv [MTOT*C3];
__device__ float g_attn[MTOT*CCH];
__device__ float g_q   [MTOT*CCH];
__device__ float g_ck  [MCTX*CCH];
__device__ float g_cv  [MCTX*CCH];
__device__ float g_h1  [MTOT*F8];
__device__ float g_gg  [MTOT*F4];
// pre-rounded (tf32) weights in [K][N] layout + context copy
__device__ float g_wc1 [CCH*CCH];
__device__ float g_wsi [CCH*C3];
__device__ float g_wso [CCH*CCH];
__device__ float g_wcq [CCH*CCH];
__device__ float g_wck [DCTX*CCH];
__device__ float g_wcv [DCTX*CCH];
__device__ float g_wco [CCH*CCH];
__device__ float g_wl1 [CCH*F8];
__device__ float g_wl2 [F4*CCH];
__device__ float g_wfin[CCH*CCH];
__device__ float g_ctx [MCTX*DCTX];

// -------- helpers --------
__device__ __forceinline__ float tf32r(float v) {
    uint32_t u;
    asm("cvt.rna.tf32.f32 %0, %1;" : "=r"(u) : "f"(v));
    return __uint_as_float(u);
}
__device__ __forceinline__ void cpa16(float* smem, const float* g, int sz) {
    uint32_t s = (uint32_t)__cvta_generic_to_shared(smem);
    asm volatile("cp.async.cg.shared.global [%0], [%1], 16, %2;" :: "r"(s), "l"(g), "r"(sz));
}
__device__ __forceinline__ void cpa_commit() {
    asm volatile("cp.async.commit_group;");
}

// -------- weight prep: round to tf32, output [K][N] --------
// trans=1: input stored [N][K]; trans=0: input stored [K][N]
__global__ void prep_round(const float* __restrict__ W, float* __restrict__ O,
                           int K, int N, int trans)
{
    long long idx = (long long)blockIdx.x * 256 + threadIdx.x;
    if (idx < (long long)K * N) {
        int k = (int)(idx / N), n = (int)(idx % N);
        float v = trans ? W[(size_t)n * K + k] : W[idx];
        O[idx] = tf32r(v);
    }
}

// -------- GroupNorm -> tf32-rounded [n,p,c] --------
__global__ __launch_bounds__(256) void gn_kernel(
    const float* __restrict__ x, const float* __restrict__ s,
    const float* __restrict__ b, float* __restrict__ out)
{
    const int g = blockIdx.x;
    const int n = blockIdx.y;
    const int cpg = CCH / 32;
    const int cnt = cpg * HW;
    const float* xp = x + ((size_t)n * CCH + (size_t)g * cpg) * HW;

    float sum = 0.f, sq = 0.f;
    for (int i = threadIdx.x; i < cnt; i += 256) {
        float v = xp[i]; sum += v; sq += v * v;
    }
    __shared__ float ss[8], sv[8];
    int lane = threadIdx.x & 31, wid = threadIdx.x >> 5;
    #pragma unroll
    for (int o = 16; o > 0; o >>= 1) {
        sum += __shfl_xor_sync(0xffffffffu, sum, o);
        sq  += __shfl_xor_sync(0xffffffffu, sq,  o);
    }
    if (lane == 0) { ss[wid] = sum; sv[wid] = sq; }
    __syncthreads();
    if (threadIdx.x == 0) {
        float ts = 0.f, tq = 0.f;
        #pragma unroll
        for (int w = 0; w < 8; w++) { ts += ss[w]; tq += sv[w]; }
        ss[0] = ts; sv[0] = tq;
    }
    __syncthreads();
    float mu  = ss[0] / (float)cnt;
    float var = sv[0] / (float)cnt - mu * mu;
    float inv = rsqrtf(var + 1e-6f);

    for (int i = threadIdx.x; i < cnt; i += 256) {
        int cl = i >> 10, p = i & 1023;
        int c  = g * cpg + cl;
        float v = (xp[i] - mu) * inv * s[c] + b[c];
        out[((size_t)n * HW + p) * CCH + c] = tf32r(v);
    }
}

// -------- LayerNorm -> tf32-rounded --------
__global__ __launch_bounds__(256) void ln_kernel(
    const float* __restrict__ x, const float* __restrict__ s,
    const float* __restrict__ b, float* __restrict__ out)
{
    const size_t row = blockIdx.x;
    const float* xp = x + row * CCH;
    float sum = 0.f, sq = 0.f;
    for (int i = threadIdx.x; i < CCH; i += 256) {
        float v = xp[i]; sum += v; sq += v * v;
    }
    __shared__ float ss[8], sv[8];
    int lane = threadIdx.x & 31, wid = threadIdx.x >> 5;
    #pragma unroll
    for (int o = 16; o > 0; o >>= 1) {
        sum += __shfl_xor_sync(0xffffffffu, sum, o);
        sq  += __shfl_xor_sync(0xffffffffu, sq,  o);
    }
    if (lane == 0) { ss[wid] = sum; sv[wid] = sq; }
    __syncthreads();
    if (threadIdx.x == 0) {
        float ts = 0.f, tq = 0.f;
        #pragma unroll
        for (int w = 0; w < 8; w++) { ts += ss[w]; tq += sv[w]; }
        ss[0] = ts; sv[0] = tq;
    }
    __syncthreads();
    float mu  = ss[0] / (float)CCH;
    float var = sv[0] / (float)CCH - mu * mu;
    float inv = rsqrtf(var + 1e-5f);
    for (int i = threadIdx.x; i < CCH; i += 256)
        out[row * CCH + i] = tf32r((xp[i] - mu) * inv * s[i] + b[i]);
}

// -------- TF32 tensor-core GEMM, cp.async 4-stage, pre-rounded inputs --------
__global__ __launch_bounds__(256) void gemm_tf32(
    const float* __restrict__ A, const float* __restrict__ B,
    const float* __restrict__ bias, const float* __restrict__ R,
    float* __restrict__ Cout, int M, int N, int K, int out_trans, int round_out)
{
    extern __shared__ float sm[];
    float* As = sm;                       // [STAGES][128][AP]
    float* Bs = sm + STAGES * A_STG;      // [STAGES][16][BP]

    const int tid  = threadIdx.x;
    const int wid  = tid >> 5, lane = tid & 31;
    const int g    = lane >> 2, tg = lane & 3;
    const int wm   = (wid >> 2) * 64;
    const int wn   = (wid & 3) * 32;
    const int m0   = blockIdx.y * 128, n0 = blockIdx.x * 128;

    const int arow = tid >> 1;
    const int acol = (tid & 1) * 8;
    const int brow = tid >> 4;
    const int bcol = (tid & 15) * 8;

    const int a_ok = (m0 + arow < M) ? 16 : 0;
    const int a_row_safe = (m0 + arow < M) ? (m0 + arow) : 0;

    float acc[4][4][4];
    #pragma unroll
    for (int i = 0; i < 4; i++)
        #pragma unroll
        for (int j = 0; j < 4; j++)
            #pragma unroll
            for (int c = 0; c < 4; c++) acc[i][j][c] = 0.f;

    auto issue = [&](int slot, int kt) {
        const int k0 = kt << 4;
        const float* ag = &A[(size_t)a_row_safe * K + k0 + acol];
        float* ad = &As[slot * A_STG + arow * AP + acol];
        cpa16(ad,     ag,     a_ok);
        cpa16(ad + 4, ag + 4, a_ok);
        const float* bg = &B[(size_t)(k0 + brow) * N + n0 + bcol];
        float* bd = &Bs[slot * B_STG + brow * BP + bcol];
        cpa16(bd,     bg,     16);
        cpa16(bd + 4, bg + 4, 16);
        cpa_commit();
    };

    const int nst = K >> 4;
    issue(0, 0);
    if (1 < nst) issue(1, 1);
    if (2 < nst) issue(2, 2);

    for (int t = 0; t < nst; t++) {
        const int slot = t & 3;
        if (t + 2 < nst)      asm volatile("cp.async.wait_group 2;");
        else if (t + 1 < nst) asm volatile("cp.async.wait_group 1;");
        else                  asm volatile("cp.async.wait_group 0;");
        __syncthreads();

        if (t + 3 < nst) issue((t + 3) & 3, t + 3);

        const float* Ac = &As[slot * A_STG];
        const float* Bc = &Bs[slot * B_STG];
        #pragma unroll
        for (int c = 0; c < 2; c++) {
            uint32_t bf[4][2];
            #pragma unroll
            for (int nj = 0; nj < 4; nj++) {
                bf[nj][0] = __float_as_uint(Bc[(c*8 + tg    ) * BP + wn + nj*8 + g]);
                bf[nj][1] = __float_as_uint(Bc[(c*8 + tg + 4) * BP + wn + nj*8 + g]);
            }
            #pragma unroll
            for (int mi = 0; mi < 4; mi++) {
                uint32_t a0 = __float_as_uint(Ac[(wm + mi*16 + g    ) * AP + c*8 + tg    ]);
                uint32_t a1 = __float_as_uint(Ac[(wm + mi*16 + g + 8) * AP + c*8 + tg    ]);
                uint32_t a2 = __float_as_uint(Ac[(wm + mi*16 + g    ) * AP + c*8 + tg + 4]);
                uint32_t a3 = __float_as_uint(Ac[(wm + mi*16 + g + 8) * AP + c*8 + tg + 4]);
                #pragma unroll
                for (int nj = 0; nj < 4; nj++) {
                    asm volatile(
                        "mma.sync.aligned.m16n8k8.row.col.f32.tf32.tf32.f32 "
                        "{%0,%1,%2,%3}, {%4,%5,%6,%7}, {%8,%9}, {%0,%1,%2,%3};"
                        : "+f"(acc[mi][nj][0]), "+f"(acc[mi][nj][1]),
                          "+f"(acc[mi][nj][2]), "+f"(acc[mi][nj][3])
                        : "r"(a0), "r"(a1), "r"(a2), "r"(a3),
                          "r"(bf[nj][0]), "r"(bf[nj][1]));
                }
            }
        }
    }

    __syncthreads();

    // epilogue: c0:(g, tg*2) c1:(g, tg*2+1) c2:(g+8, tg*2) c3:(g+8, tg*2+1)
    #pragma unroll
    for (int mi = 0; mi < 4; mi++) {
        #pragma unroll
        for (int r = 0; r < 2; r++) {
            int m = m0 + wm + mi*16 + g + r*8;
            if (m >= M) continue;
            #pragma unroll
            for (int nj = 0; nj < 4; nj++) {
                int n = n0 + wn + nj*8 + tg*2;
                float v0 = acc[mi][nj][r*2 + 0];
                float v1 = acc[mi][nj][r*2 + 1];
                if (bias) { v0 += bias[n]; v1 += bias[n+1]; }
                size_t i0, i1;
                if (out_trans) {
                    int nb = m >> 10, p = m & 1023;
                    i0 = ((size_t)nb * N + n) * 1024 + p;
                    i1 = i0 + 1024;
                } else {
                    i0 = (size_t)m * N + n;
                    i1 = i0 + 1;
                }
                if (R) { v0 += R[i0]; v1 += R[i1]; }
                if (round_out) { v0 = tf32r(v0); v1 = tf32r(v1); }
                Cout[i0] = v0;
                Cout[i1] = v1;
            }
        }
    }
}

// -------- flash-style tiled attention (fp32; output tf32-rounded) --------
__global__ __launch_bounds__(256) void fattn_kernel(
    const float* __restrict__ Q, const float* __restrict__ K,
    const float* __restrict__ V, float* __restrict__ O,
    int seq_kv, int qs, int ks, int vs, int os,
    long long qbs, long long kbs, long long vbs, long long obs)
{
    extern __shared__ float smf[];
    float* Qs = smf;
    float* Ks = Qs + QT*QP;
    float* Vs = Ks + KT*QP;
    float* Ps = Vs + KT*QP;

    const int qt = blockIdx.x, h = blockIdx.y, b = blockIdx.z;
    const int tid = threadIdx.x;
    const int ty = tid >> 4, tx = tid & 15;

    const float* qp = Q + (size_t)b * qbs + (size_t)h * DH;
    const float* kp = K + (size_t)b * kbs + (size_t)h * DH;
    const float* vp = V + (size_t)b * vbs + (size_t)h * DH;
    float*       op = O + (size_t)b * obs + (size_t)h * DH;

    for (int i = tid; i < QT*DH; i += 256) {
        int r = i / DH, d = i - r*DH;
        Qs[r*QP + d] = qp[(size_t)(qt*QT + r) * qs + d];
    }

    float m[4], l[4], o[4][5];
    #pragma unroll
    for (int i = 0; i < 4; i++) {
        m[i] = -1e30f; l[i] = 0.f;
        #pragma unroll
        for (int j = 0; j < 5; j++) o[i][j] = 0.f;
    }

    const float scale = 0.11180339887498949f;
    const int ntile = (seq_kv + KT - 1) / KT;

    for (int t = 0; t < ntile; t++) {
        const int k0 = t * KT;
        __syncthreads();
        for (int i = tid; i < KT*DH; i += 256) {
            int r = i / DH, d = i - r*DH;
            int kg = k0 + r;
            float kv = 0.f, vv = 0.f;
            if (kg < seq_kv) {
                kv = kp[(size_t)kg * ks + d];
                vv = vp[(size_t)kg * vs + d];
            }
            Ks[r*QP + d] = kv;
            Vs[r*QP + d] = vv;
        }
        __syncthreads();

        float s[4][4] = {};
        for (int d = 0; d < DH; d++) {
            float qv[4], kv[4];
            #pragma unroll
            for (int i = 0; i < 4; i++) qv[i] = Qs[(ty*4+i)*QP + d];
            #pragma unroll
            for (int j = 0; j < 4; j++) kv[j] = Ks[(tx*4+j)*QP + d];
            #pragma unroll
            for (int i = 0; i < 4; i++)
                #pragma unroll
                for (int j = 0; j < 4; j++)
                    s[i][j] += qv[i] * kv[j];
        }
        #pragma unroll
        for (int i = 0; i < 4; i++)
            #pragma unroll
            for (int j = 0; j < 4; j++) {
                s[i][j] *= scale;
                if (k0 + tx*4 + j >= seq_kv) s[i][j] = -1e30f;
            }

        #pragma unroll
        for (int i = 0; i < 4; i++) {
            float mt = fmaxf(fmaxf(s[i][0], s[i][1]), fmaxf(s[i][2], s[i][3]));
            #pragma unroll
            for (int off = 8; off > 0; off >>= 1)
                mt = fmaxf(mt, __shfl_xor_sync(0xffffffffu, mt, off));
            float mn = fmaxf(m[i], mt);
            float f  = __expf(m[i] - mn);
            m[i] = mn;
            float rs = 0.f;
            #pragma unroll
            for (int j = 0; j < 4; j++) {
                float p = __expf(s[i][j] - mn);
                s[i][j] = p;
                rs += p;
            }
            #pragma unroll
            for (int off = 8; off > 0; off >>= 1)
                rs += __shfl_xor_sync(0xffffffffu, rs, off);
            l[i] = l[i] * f + rs;
            #pragma unroll
            for (int j = 0; j < 5; j++) o[i][j] *= f;
        }

        #pragma unroll
        for (int i = 0; i < 4; i++)
            #pragma unroll
            for (int j = 0; j < 4; j++)
                Ps[(ty*4+i)*PP + tx*4+j] = s[i][j];
        __syncthreads();

        for (int k = 0; k < KT; k++) {
            float pv[4], vv[5];
            #pragma unroll
            for (int i = 0; i < 4; i++) pv[i] = Ps[(ty*4+i)*PP + k];
            #pragma unroll
            for (int j = 0; j < 5; j++) vv[j] = Vs[k*QP + tx*5+j];
            #pragma unroll
            for (int i = 0; i < 4; i++)
                #pragma unroll
                for (int j = 0; j < 5; j++)
                    o[i][j] += pv[i] * vv[j];
        }
    }

    #pragma unroll
    for (int i = 0; i < 4; i++) {
        float inv = 1.f / l[i];
        int qg = qt*QT + ty*4 + i;
        #pragma unroll
        for (int j = 0; j < 5; j++)
            op[(size_t)qg * os + tx*5 + j] = tf32r(o[i][j] * inv);
    }
}

// -------- GeGLU -> tf32-rounded --------
__global__ __launch_bounds__(256) void geglu_kernel(
    const float* __restrict__ h1, float* __restrict__ g)
{
    size_t i = (size_t)blockIdx.x * 256 + threadIdx.x;
    if (i < (size_t)MTOT * F4) {
        size_t row = i / F4, j = i % F4;
        float a  = h1[row * F8 + j];
        float x  = h1[row * F8 + F4 + j];
        float ge = 0.5f * x * (1.0f + erff(x * 0.70710678118654752f));
        g[i] = tf32r(a * ge);
    }
}

extern "C" void kernel_launch(void* const* d_in, const int* in_sizes, int n_in,
                              void* d_out, int out_size)
{
    const float* x       = (const float*)d_in[0];
    const float* context = (const float*)d_in[1];
    const float* gn_s    = (const float*)d_in[2];
    const float* gn_b    = (const float*)d_in[3];
    const float* conv1_w = (const float*)d_in[4];
    const float* conv1_b = (const float*)d_in[5];
    const float* ln1_s   = (const float*)d_in[6];
    const float* ln1_b   = (const float*)d_in[7];
    const float* sa_in_w = (const float*)d_in[8];
    const float* sa_out_w= (const float*)d_in[9];
    const float* sa_out_b= (const float*)d_in[10];
    const float* ln2_s   = (const float*)d_in[11];
    const float* ln2_b   = (const float*)d_in[12];
    const float* ca_q_w  = (const float*)d_in[13];
    const float* ca_k_w  = (const float*)d_in[14];
    const float* ca_v_w  = (const float*)d_in[15];
    const float* ca_out_w= (const float*)d_in[16];
    const float* ca_out_b= (const float*)d_in[17];
    const float* ln3_s   = (const float*)d_in[18];
    const float* ln3_b   = (const float*)d_in[19];
    const float* lin1_w  = (const float*)d_in[20];
    const float* lin1_b  = (const float*)d_in[21];
    const float* lin2_w  = (const float*)d_in[22];
    const float* lin2_b  = (const float*)d_in[23];
    const float* co_w    = (const float*)d_in[24];
    const float* co_b    = (const float*)d_in[25];
    float* out = (float*)d_out;

    float *gnt, *xseq, *t, *qkv, *attn, *qb, *ck, *cv, *h1, *gg;
    float *wc1, *wsi, *wso, *wcq, *wck, *wcv, *wco, *wl1, *wl2, *wfin, *ctx;
    cudaGetSymbolAddress((void**)&gnt,  g_gnt);
    cudaGetSymbolAddress((void**)&xseq, g_xseq);
    cudaGetSymbolAddress((void**)&t,    g_t);
    cudaGetSymbolAddress((void**)&qkv,  g_qkv);
    cudaGetSymbolAddress((void**)&attn, g_attn);
    cudaGetSymbolAddress((void**)&qb,   g_q);
    cudaGetSymbolAddress((void**)&ck,   g_ck);
    cudaGetSymbolAddress((void**)&cv,   g_cv);
    cudaGetSymbolAddress((void**)&h1,   g_h1);
    cudaGetSymbolAddress((void**)&gg,   g_gg);
    cudaGetSymbolAddress((void**)&wc1,  g_wc1);
    cudaGetSymbolAddress((void**)&wsi,  g_wsi);
    cudaGetSymbolAddress((void**)&wso,  g_wso);
    cudaGetSymbolAddress((void**)&wcq,  g_wcq);
    cudaGetSymbolAddress((void**)&wck,  g_wck);
    cudaGetSymbolAddress((void**)&wcv,  g_wcv);
    cudaGetSymbolAddress((void**)&wco,  g_wco);
    cudaGetSymbolAddress((void**)&wl1,  g_wl1);
    cudaGetSymbolAddress((void**)&wl2,  g_wl2);
    cudaGetSymbolAddress((void**)&wfin, g_wfin);
    cudaGetSymbolAddress((void**)&ctx,  g_ctx);

    cudaFuncSetAttribute(fattn_kernel, cudaFuncAttributeMaxDynamicSharedMemorySize, SMEM_ATTN);
    cudaFuncSetAttribute(gemm_tf32,   cudaFuncAttributeMaxDynamicSharedMemorySize, SMEM_GEMM);

    #define PREP(W, O, KK, NN, TR) \
        prep_round<<<(unsigned)(((long long)(KK)*(NN) + 255) / 256), 256>>>(W, O, KK, NN, TR)

    // weights -> tf32-rounded [K][N]
    PREP(conv1_w, wc1,  CCH,  CCH, 1);   // [out][in] -> transpose
    PREP(sa_in_w, wsi,  CCH,  C3,  0);   // already [K][N]
    PREP(sa_out_w,wso,  CCH,  CCH, 0);
    PREP(ca_q_w,  wcq,  CCH,  CCH, 0);
    PREP(ca_k_w,  wck,  DCTX, CCH, 0);
    PREP(ca_v_w,  wcv,  DCTX, CCH, 0);
    PREP(ca_out_w,wco,  CCH,  CCH, 0);
    PREP(lin1_w,  wl1,  CCH,  F8,  0);
    PREP(lin2_w,  wl2,  F4,   CCH, 0);
    PREP(co_w,    wfin, CCH,  CCH, 1);   // [out][in] -> transpose
    PREP(context, ctx,  MCTX, DCTX, 0);  // row-major round copy

    gn_kernel<<<dim3(32, NB), 256>>>(x, gn_s, gn_b, gnt);

    #define GTC(A_,B_,bias_,R_,O_,M_,N_,K_,TR_,RO_) \
        gemm_tf32<<<dim3((N_)/128, ((M_)+127)/128), 256, SMEM_GEMM>>>(A_,B_,bias_,R_,O_,M_,N_,K_,TR_,RO_)

    // conv1
    GTC(gnt, wc1, conv1_b, nullptr, xseq, MTOT, CCH, CCH, 0, 0);

    // ---- self-attention ----
    ln_kernel<<<MTOT, 256>>>(xseq, ln1_s, ln1_b, t);
    GTC(t, wsi, nullptr, nullptr, qkv, MTOT, C3, CCH, 0, 0);
    fattn_kernel<<<dim3(HW/QT, NH, NB), 256, SMEM_ATTN>>>(
        qkv, qkv + CCH, qkv + 2 * CCH, attn,
        HW, C3, C3, C3, CCH,
        (long long)HW * C3, (long long)HW * C3,
        (long long)HW * C3, (long long)HW * CCH);
    GTC(attn, wso, sa_out_b, xseq, xseq, MTOT, CCH, CCH, 0, 0);

    // ---- cross-attention ----
    ln_kernel<<<MTOT, 256>>>(xseq, ln2_s, ln2_b, t);
    GTC(t, wcq, nullptr, nullptr, qb, MTOT, CCH, CCH, 0, 0);
    GTC(ctx, wck, nullptr, nullptr, ck, MCTX, CCH, DCTX, 0, 0);
    GTC(ctx, wcv, nullptr, nullptr, cv, MCTX, CCH, DCTX, 0, 0);
    fattn_kernel<<<dim3(HW/QT, NH, NB), 256, SMEM_ATTN>>>(
        qb, ck, cv, attn,
        CTXL, CCH, CCH, CCH, CCH,
        (long long)HW * CCH, (long long)CTXL * CCH,
        (long long)CTXL * CCH, (long long)HW * CCH);
    GTC(attn, wco, ca_out_b, xseq, xseq, MTOT, CCH, CCH, 0, 0);

    // ---- GeGLU FFN ----
    ln_kernel<<<MTOT, 256>>>(xseq, ln3_s, ln3_b, t);
    GTC(t, wl1, lin1_b, nullptr, h1, MTOT, F8, CCH, 0, 0);
    geglu_kernel<<<(unsigned)(((size_t)MTOT * F4 + 255) / 256), 256>>>(h1, gg);
    GTC(gg, wl2, lin2_b, xseq, xseq, MTOT, CCH, F4, 0, 1);  // round: feeds final GEMM A

    // ---- output conv + long residual ----
    GTC(xseq, wfin, co_b, x, out, MTOT, CCH, CCH, 1, 0);
}

// round 13
// speedup vs baseline: 10.0372x; 1.0997x over previous
#include <cuda_runtime.h>
#include <math.h>
#include <stdint.h>

#define NB   8
#define CCH  640
#define HW   1024
#define C3   1920
#define NH   8
#define DH   80
#define CTXL 77
#define DCTX 512
#define F8   5120
#define F4   2560
#define MTOT (NB*HW)   // 8192
#define MCTX (NB*CTXL) // 616

// attention tiling
#define QT 64
#define KT 64
#define QP 81
#define PP 65
#define SMEM_ATTN ((3*QT*QP + QT*PP)*4)

// GEMM pipeline
#define STAGES 3
#define AP 20                      // A smem pitch (floats)
#define BP 136                     // B smem pitch (floats)
#define A_STG (128*AP)
#define B_STG (16*BP)
#define SMEM_GEMM ((STAGES*(A_STG + B_STG))*4)   // 56832 B

// -------- scratch --------
__device__ float g_gnt [MTOT*CCH];
__device__ float g_xseq[MTOT*CCH];
__device__ float g_t   [MTOT*CCH];
__device__ float g_qkv [MTOT*C3];
__device__ float g_attn[MTOT*CCH];
__device__ float g_q   [MTOT*CCH];
__device__ float g_ck  [MCTX*CCH];
__device__ float g_cv  [MCTX*CCH];
__device__ float g_h1  [MTOT*F8];
__device__ float g_gg  [MTOT*F4];
// pre-rounded (tf32) weights in [K][N] layout + context copy
__device__ float g_wc1 [CCH*CCH];
__device__ float g_wsi [CCH*C3];
__device__ float g_wso [CCH*CCH];
__device__ float g_wcq [CCH*CCH];
__device__ float g_wck [DCTX*CCH];
__device__ float g_wcv [DCTX*CCH];
__device__ float g_wco [CCH*CCH];
__device__ float g_wl1 [CCH*F8];
__device__ float g_wl2 [F4*CCH];
__device__ float g_wfin[CCH*CCH];
__device__ float g_ctx [MCTX*DCTX];

// -------- helpers --------
__device__ __forceinline__ float tf32r(float v) {
    uint32_t u;
    asm("cvt.rna.tf32.f32 %0, %1;" : "=r"(u) : "f"(v));
    return __uint_as_float(u);
}
__device__ __forceinline__ void cpa16(float* smem, const float* g, int sz) {
    uint32_t s = (uint32_t)__cvta_generic_to_shared(smem);
    asm volatile("cp.async.cg.shared.global [%0], [%1], 16, %2;" :: "r"(s), "l"(g), "r"(sz));
}
__device__ __forceinline__ void cpa_commit() {
    asm volatile("cp.async.commit_group;");
}

// -------- weight prep: round to tf32, output [K][N] --------
__global__ void prep_round(const float* __restrict__ W, float* __restrict__ O,
                           int K, int N, int trans)
{
    long long idx = (long long)blockIdx.x * 256 + threadIdx.x;
    if (idx < (long long)K * N) {
        int k = (int)(idx / N), n = (int)(idx % N);
        float v = trans ? W[(size_t)n * K + k] : W[idx];
        O[idx] = tf32r(v);
    }
}

// -------- GroupNorm -> tf32-rounded [n,p,c] --------
__global__ __launch_bounds__(256) void gn_kernel(
    const float* __restrict__ x, const float* __restrict__ s,
    const float* __restrict__ b, float* __restrict__ out)
{
    const int g = blockIdx.x;
    const int n = blockIdx.y;
    const int cpg = CCH / 32;
    const int cnt = cpg * HW;
    const float* xp = x + ((size_t)n * CCH + (size_t)g * cpg) * HW;

    float sum = 0.f, sq = 0.f;
    for (int i = threadIdx.x; i < cnt; i += 256) {
        float v = xp[i]; sum += v; sq += v * v;
    }
    __shared__ float ss[8], sv[8];
    int lane = threadIdx.x & 31, wid = threadIdx.x >> 5;
    #pragma unroll
    for (int o = 16; o > 0; o >>= 1) {
        sum += __shfl_xor_sync(0xffffffffu, sum, o);
        sq  += __shfl_xor_sync(0xffffffffu, sq,  o);
    }
    if (lane == 0) { ss[wid] = sum; sv[wid] = sq; }
    __syncthreads();
    if (threadIdx.x == 0) {
        float ts = 0.f, tq = 0.f;
        #pragma unroll
        for (int w = 0; w < 8; w++) { ts += ss[w]; tq += sv[w]; }
        ss[0] = ts; sv[0] = tq;
    }
    __syncthreads();
    float mu  = ss[0] / (float)cnt;
    float var = sv[0] / (float)cnt - mu * mu;
    float inv = rsqrtf(var + 1e-6f);

    for (int i = threadIdx.x; i < cnt; i += 256) {
        int cl = i >> 10, p = i & 1023;
        int c  = g * cpg + cl;
        float v = (xp[i] - mu) * inv * s[c] + b[c];
        out[((size_t)n * HW + p) * CCH + c] = tf32r(v);
    }
}

// -------- LayerNorm -> tf32-rounded --------
__global__ __launch_bounds__(256) void ln_kernel(
    const float* __restrict__ x, const float* __restrict__ s,
    const float* __restrict__ b, float* __restrict__ out)
{
    const size_t row = blockIdx.x;
    const float* xp = x + row * CCH;
    float sum = 0.f, sq = 0.f;
    for (int i = threadIdx.x; i < CCH; i += 256) {
        float v = xp[i]; sum += v; sq += v * v;
    }
    __shared__ float ss[8], sv[8];
    int lane = threadIdx.x & 31, wid = threadIdx.x >> 5;
    #pragma unroll
    for (int o = 16; o > 0; o >>= 1) {
        sum += __shfl_xor_sync(0xffffffffu, sum, o);
        sq  += __shfl_xor_sync(0xffffffffu, sq,  o);
    }
    if (lane == 0) { ss[wid] = sum; sv[wid] = sq; }
    __syncthreads();
    if (threadIdx.x == 0) {
        float ts = 0.f, tq = 0.f;
        #pragma unroll
        for (int w = 0; w < 8; w++) { ts += ss[w]; tq += sv[w]; }
        ss[0] = ts; sv[0] = tq;
    }
    __syncthreads();
    float mu  = ss[0] / (float)CCH;
    float var = sv[0] / (float)CCH - mu * mu;
    float inv = rsqrtf(var + 1e-5f);
    for (int i = threadIdx.x; i < CCH; i += 256)
        out[row * CCH + i] = tf32r((xp[i] - mu) * inv * s[i] + b[i]);
}

// -------- TF32 tensor-core GEMM: 128-thread CTA, 4 warps, 64x64 warp tile --------
__global__ __launch_bounds__(128) void gemm_tf32(
    const float* __restrict__ A, const float* __restrict__ B,
    const float* __restrict__ bias, const float* __restrict__ R,
    float* __restrict__ Cout, int M, int N, int K, int out_trans, int round_out)
{
    extern __shared__ float sm[];
    float* As = sm;                       // [STAGES][128][AP]
    float* Bs = sm + STAGES * A_STG;      // [STAGES][16][BP]

    const int tid  = threadIdx.x;
    const int wid  = tid >> 5, lane = tid & 31;
    const int g    = lane >> 2, tg = lane & 3;
    const int wm   = (wid >> 1) * 64;
    const int wn   = (wid & 1) * 64;
    const int m0   = blockIdx.y * 128, n0 = blockIdx.x * 128;

    float acc[4][8][4];
    #pragma unroll
    for (int i = 0; i < 4; i++)
        #pragma unroll
        for (int j = 0; j < 8; j++)
            #pragma unroll
            for (int c = 0; c < 4; c++) acc[i][j][c] = 0.f;

    auto issue = [&](int slot, int kt) {
        const int k0 = kt << 4;
        float* Ab = &As[slot * A_STG];
        float* Bb = &Bs[slot * B_STG];
        #pragma unroll
        for (int it = 0; it < 4; it++) {
            int idx = it * 128 + tid;
            int row = idx >> 2, kc = (idx & 3) * 4;
            int mg = m0 + row;
            int ok = (mg < M) ? 16 : 0;
            const float* ag = &A[(size_t)(ok ? mg : 0) * K + k0 + kc];
            cpa16(&Ab[row * AP + kc], ag, ok);
        }
        #pragma unroll
        for (int it = 0; it < 4; it++) {
            int idx = it * 128 + tid;
            int kr = idx >> 5, nc = (idx & 31) * 4;
            const float* bg = &B[(size_t)(k0 + kr) * N + n0 + nc];
            cpa16(&Bb[kr * BP + nc], bg, 16);
        }
        cpa_commit();
    };

    const int nst = K >> 4;
    issue(0, 0);
    if (1 < nst) issue(1, 1);

    for (int t = 0; t < nst; t++) {
        const int slot = t % STAGES;
        if (t + 1 < nst) asm volatile("cp.async.wait_group 1;");
        else             asm volatile("cp.async.wait_group 0;");
        __syncthreads();

        if (t + 2 < nst) issue((t + 2) % STAGES, t + 2);

        const float* Ac = &As[slot * A_STG];
        const float* Bc = &Bs[slot * B_STG];
        #pragma unroll
        for (int c = 0; c < 2; c++) {
            uint32_t bf[8][2];
            #pragma unroll
            for (int nj = 0; nj < 8; nj++) {
                bf[nj][0] = __float_as_uint(Bc[(c*8 + tg    ) * BP + wn + nj*8 + g]);
                bf[nj][1] = __float_as_uint(Bc[(c*8 + tg + 4) * BP + wn + nj*8 + g]);
            }
            #pragma unroll
            for (int mi = 0; mi < 4; mi++) {
                uint32_t a0 = __float_as_uint(Ac[(wm + mi*16 + g    ) * AP + c*8 + tg    ]);
                uint32_t a1 = __float_as_uint(Ac[(wm + mi*16 + g + 8) * AP + c*8 + tg    ]);
                uint32_t a2 = __float_as_uint(Ac[(wm + mi*16 + g    ) * AP + c*8 + tg + 4]);
                uint32_t a3 = __float_as_uint(Ac[(wm + mi*16 + g + 8) * AP + c*8 + tg + 4]);
                #pragma unroll
                for (int nj = 0; nj < 8; nj++) {
                    asm volatile(
                        "mma.sync.aligned.m16n8k8.row.col.f32.tf32.tf32.f32 "
                        "{%0,%1,%2,%3}, {%4,%5,%6,%7}, {%8,%9}, {%0,%1,%2,%3};"
                        : "+f"(acc[mi][nj][0]), "+f"(acc[mi][nj][1]),
                          "+f"(acc[mi][nj][2]), "+f"(acc[mi][nj][3])
                        : "r"(a0), "r"(a1), "r"(a2), "r"(a3),
                          "r"(bf[nj][0]), "r"(bf[nj][1]));
                }
            }
        }
    }

    __syncthreads();

    // epilogue: c0:(g, tg*2) c1:(g, tg*2+1) c2:(g+8, tg*2) c3:(g+8, tg*2+1)
    #pragma unroll
    for (int mi = 0; mi < 4; mi++) {
        #pragma unroll
        for (int r = 0; r < 2; r++) {
            int m = m0 + wm + mi*16 + g + r*8;
            if (m >= M) continue;
            #pragma unroll
            for (int nj = 0; nj < 8; nj++) {
                int n = n0 + wn + nj*8 + tg*2;
                float v0 = acc[mi][nj][r*2 + 0];
                float v1 = acc[mi][nj][r*2 + 1];
                if (bias) { v0 += bias[n]; v1 += bias[n+1]; }
                size_t i0, i1;
                if (out_trans) {
                    int nb = m >> 10, p = m & 1023;
                    i0 = ((size_t)nb * N + n) * 1024 + p;
                    i1 = i0 + 1024;
                } else {
                    i0 = (size_t)m * N + n;
                    i1 = i0 + 1;
                }
                if (R) { v0 += R[i0]; v1 += R[i1]; }
                if (round_out) { v0 = tf32r(v0); v1 = tf32r(v1); }
                Cout[i0] = v0;
                Cout[i1] = v1;
            }
        }
    }
}

// -------- flash-style tiled attention (fp32; output tf32-rounded) --------
__global__ __launch_bounds__(256) void fattn_kernel(
    const float* __restrict__ Q, const float* __restrict__ K,
    const float* __restrict__ V, float* __restrict__ O,
    int seq_kv, int qs, int ks, int vs, int os,
    long long qbs, long long kbs, long long vbs, long long obs)
{
    extern __shared__ float smf[];
    float* Qs = smf;
    float* Ks = Qs + QT*QP;
    float* Vs = Ks + KT*QP;
    float* Ps = Vs + KT*QP;

    const int qt = blockIdx.x, h = blockIdx.y, b = blockIdx.z;
    const int tid = threadIdx.x;
    const int ty = tid >> 4, tx = tid & 15;

    const float* qp = Q + (size_t)b * qbs + (size_t)h * DH;
    const float* kp = K + (size_t)b * kbs + (size_t)h * DH;
    const float* vp = V + (size_t)b * vbs + (size_t)h * DH;
    float*       op = O + (size_t)b * obs + (size_t)h * DH;

    for (int i = tid; i < QT*DH; i += 256) {
        int r = i / DH, d = i - r*DH;
        Qs[r*QP + d] = qp[(size_t)(qt*QT + r) * qs + d];
    }

    float m[4], l[4], o[4][5];
    #pragma unroll
    for (int i = 0; i < 4; i++) {
        m[i] = -1e30f; l[i] = 0.f;
        #pragma unroll
        for (int j = 0; j < 5; j++) o[i][j] = 0.f;
    }

    const float scale = 0.11180339887498949f;
    const int ntile = (seq_kv + KT - 1) / KT;

    for (int t = 0; t < ntile; t++) {
        const int k0 = t * KT;
        __syncthreads();
        for (int i = tid; i < KT*DH; i += 256) {
            int r = i / DH, d = i - r*DH;
            int kg = k0 + r;
            float kv = 0.f, vv = 0.f;
            if (kg < seq_kv) {
                kv = kp[(size_t)kg * ks + d];
                vv = vp[(size_t)kg * vs + d];
            }
            Ks[r*QP + d] = kv;
            Vs[r*QP + d] = vv;
        }
        __syncthreads();

        float s[4][4] = {};
        for (int d = 0; d < DH; d++) {
            float qv[4], kv[4];
            #pragma unroll
            for (int i = 0; i < 4; i++) qv[i] = Qs[(ty*4+i)*QP + d];
            #pragma unroll
            for (int j = 0; j < 4; j++) kv[j] = Ks[(tx*4+j)*QP + d];
            #pragma unroll
            for (int i = 0; i < 4; i++)
                #pragma unroll
                for (int j = 0; j < 4; j++)
                    s[i][j] += qv[i] * kv[j];
        }
        #pragma unroll
        for (int i = 0; i < 4; i++)
            #pragma unroll
            for (int j = 0; j < 4; j++) {
                s[i][j] *= scale;
                if (k0 + tx*4 + j >= seq_kv) s[i][j] = -1e30f;
            }

        #pragma unroll
        for (int i = 0; i < 4; i++) {
            float mt = fmaxf(fmaxf(s[i][0], s[i][1]), fmaxf(s[i][2], s[i][3]));
            #pragma unroll
            for (int off = 8; off > 0; off >>= 1)
                mt = fmaxf(mt, __shfl_xor_sync(0xffffffffu, mt, off));
            float mn = fmaxf(m[i], mt);
            float f  = __expf(m[i] - mn);
            m[i] = mn;
            float rs = 0.f;
            #pragma unroll
            for (int j = 0; j < 4; j++) {
                float p = __expf(s[i][j] - mn);
                s[i][j] = p;
                rs += p;
            }
            #pragma unroll
            for (int off = 8; off > 0; off >>= 1)
                rs += __shfl_xor_sync(0xffffffffu, rs, off);
            l[i] = l[i] * f + rs;
            #pragma unroll
            for (int j = 0; j < 5; j++) o[i][j] *= f;
        }

        #pragma unroll
        for (int i = 0; i < 4; i++)
            #pragma unroll
            for (int j = 0; j < 4; j++)
                Ps[(ty*4+i)*PP + tx*4+j] = s[i][j];
        __syncthreads();

        for (int k = 0; k < KT; k++) {
            float pv[4], vv[5];
            #pragma unroll
            for (int i = 0; i < 4; i++) pv[i] = Ps[(ty*4+i)*PP + k];
            #pragma unroll
            for (int j = 0; j < 5; j++) vv[j] = Vs[k*QP + tx*5+j];
            #pragma unroll
            for (int i = 0; i < 4; i++)
                #pragma unroll
                for (int j = 0; j < 5; j++)
                    o[i][j] += pv[i] * vv[j];
        }
    }

    #pragma unroll
    for (int i = 0; i < 4; i++) {
        float inv = 1.f / l[i];
        int qg = qt*QT + ty*4 + i;
        #pragma unroll
        for (int j = 0; j < 5; j++)
            op[(size_t)qg * os + tx*5 + j] = tf32r(o[i][j] * inv);
    }
}

// -------- GeGLU -> tf32-rounded --------
__global__ __launch_bounds__(256) void geglu_kernel(
    const float* __restrict__ h1, float* __restrict__ g)
{
    size_t i = (size_t)blockIdx.x * 256 + threadIdx.x;
    if (i < (size_t)MTOT * F4) {
        size_t row = i / F4, j = i % F4;
        float a  = h1[row * F8 + j];
        float x  = h1[row * F8 + F4 + j];
        float ge = 0.5f * x * (1.0f + erff(x * 0.70710678118654752f));
        g[i] = tf32r(a * ge);
    }
}

extern "C" void kernel_launch(void* const* d_in, const int* in_sizes, int n_in,
                              void* d_out, int out_size)
{
    const float* x       = (const float*)d_in[0];
    const float* context = (const float*)d_in[1];
    const float* gn_s    = (const float*)d_in[2];
    const float* gn_b    = (const float*)d_in[3];
    const float* conv1_w = (const float*)d_in[4];
    const float* conv1_b = (const float*)d_in[5];
    const float* ln1_s   = (const float*)d_in[6];
    const float* ln1_b   = (const float*)d_in[7];
    const float* sa_in_w = (const float*)d_in[8];
    const float* sa_out_w= (const float*)d_in[9];
    const float* sa_out_b= (const float*)d_in[10];
    const float* ln2_s   = (const float*)d_in[11];
    const float* ln2_b   = (const float*)d_in[12];
    const float* ca_q_w  = (const float*)d_in[13];
    const float* ca_k_w  = (const float*)d_in[14];
    const float* ca_v_w  = (const float*)d_in[15];
    const float* ca_out_w= (const float*)d_in[16];
    const float* ca_out_b= (const float*)d_in[17];
    const float* ln3_s   = (const float*)d_in[18];
    const float* ln3_b   = (const float*)d_in[19];
    const float* lin1_w  = (const float*)d_in[20];
    const float* lin1_b  = (const float*)d_in[21];
    const float* lin2_w  = (const float*)d_in[22];
    const float* lin2_b  = (const float*)d_in[23];
    const float* co_w    = (const float*)d_in[24];
    const float* co_b    = (const float*)d_in[25];
    float* out = (float*)d_out;

    float *gnt, *xseq, *t, *qkv, *attn, *qb, *ck, *cv, *h1, *gg;
    float *wc1, *wsi, *wso, *wcq, *wck, *wcv, *wco, *wl1, *wl2, *wfin, *ctx;
    cudaGetSymbolAddress((void**)&gnt,  g_gnt);
    cudaGetSymbolAddress((void**)&xseq, g_xseq);
    cudaGetSymbolAddress((void**)&t,    g_t);
    cudaGetSymbolAddress((void**)&qkv,  g_qkv);
    cudaGetSymbolAddress((void**)&attn, g_attn);
    cudaGetSymbolAddress((void**)&qb,   g_q);
    cudaGetSymbolAddress((void**)&ck,   g_ck);
    cudaGetSymbolAddress((void**)&cv,   g_cv);
    cudaGetSymbolAddress((void**)&h1,   g_h1);
    cudaGetSymbolAddress((void**)&gg,   g_gg);
    cudaGetSymbolAddress((void**)&wc1,  g_wc1);
    cudaGetSymbolAddress((void**)&wsi,  g_wsi);
    cudaGetSymbolAddress((void**)&wso,  g_wso);
    cudaGetSymbolAddress((void**)&wcq,  g_wcq);
    cudaGetSymbolAddress((void**)&wck,  g_wck);
    cudaGetSymbolAddress((void**)&wcv,  g_wcv);
    cudaGetSymbolAddress((void**)&wco,  g_wco);
    cudaGetSymbolAddress((void**)&wl1,  g_wl1);
    cudaGetSymbolAddress((void**)&wl2,  g_wl2);
    cudaGetSymbolAddress((void**)&wfin, g_wfin);
    cudaGetSymbolAddress((void**)&ctx,  g_ctx);

    cudaFuncSetAttribute(fattn_kernel, cudaFuncAttributeMaxDynamicSharedMemorySize, SMEM_ATTN);
    cudaFuncSetAttribute(gemm_tf32,   cudaFuncAttributeMaxDynamicSharedMemorySize, SMEM_GEMM);

    #define PREP(W, O, KK, NN, TR) \
        prep_round<<<(unsigned)(((long long)(KK)*(NN) + 255) / 256), 256>>>(W, O, KK, NN, TR)

    PREP(conv1_w, wc1,  CCH,  CCH, 1);
    PREP(sa_in_w, wsi,  CCH,  C3,  0);
    PREP(sa_out_w,wso,  CCH,  CCH, 0);
    PREP(ca_q_w,  wcq,  CCH,  CCH, 0);
    PREP(ca_k_w,  wck,  DCTX, CCH, 0);
    PREP(ca_v_w,  wcv,  DCTX, CCH, 0);
    PREP(ca_out_w,wco,  CCH,  CCH, 0);
    PREP(lin1_w,  wl1,  CCH,  F8,  0);
    PREP(lin2_w,  wl2,  F4,   CCH, 0);
    PREP(co_w,    wfin, CCH,  CCH, 1);
    PREP(context, ctx,  MCTX, DCTX, 0);

    gn_kernel<<<dim3(32, NB), 256>>>(x, gn_s, gn_b, gnt);

    #define GTC(A_,B_,bias_,R_,O_,M_,N_,K_,TR_,RO_) \
        gemm_tf32<<<dim3((N_)/128, ((M_)+127)/128), 128, SMEM_GEMM>>>(A_,B_,bias_,R_,O_,M_,N_,K_,TR_,RO_)

    // conv1
    GTC(gnt, wc1, conv1_b, nullptr, xseq, MTOT, CCH, CCH, 0, 0);

    // ---- self-attention ----
    ln_kernel<<<MTOT, 256>>>(xseq, ln1_s, ln1_b, t);
    GTC(t, wsi, nullptr, nullptr, qkv, MTOT, C3, CCH, 0, 0);
    fattn_kernel<<<dim3(HW/QT, NH, NB), 256, SMEM_ATTN>>>(
        qkv, qkv + CCH, qkv + 2 * CCH, attn,
        HW, C3, C3, C3, CCH,
        (long long)HW * C3, (long long)HW * C3,
        (long long)HW * C3, (long long)HW * CCH);
    GTC(attn, wso, sa_out_b, xseq, xseq, MTOT, CCH, CCH, 0, 0);

    // ---- cross-attention ----
    ln_kernel<<<MTOT, 256>>>(xseq, ln2_s, ln2_b, t);
    GTC(t, wcq, nullptr, nullptr, qb, MTOT, CCH, CCH, 0, 0);
    GTC(ctx, wck, nullptr, nullptr, ck, MCTX, CCH, DCTX, 0, 0);
    GTC(ctx, wcv, nullptr, nullptr, cv, MCTX, CCH, DCTX, 0, 0);
    fattn_kernel<<<dim3(HW/QT, NH, NB), 256, SMEM_ATTN>>>(
        qb, ck, cv, attn,
        CTXL, CCH, CCH, CCH, CCH,
        (long long)HW * CCH, (long long)CTXL * CCH,
        (long long)CTXL * CCH, (long long)HW * CCH);
    GTC(attn, wco, ca_out_b, xseq, xseq, MTOT, CCH, CCH, 0, 0);

    // ---- GeGLU FFN ----
    ln_kernel<<<MTOT, 256>>>(xseq, ln3_s, ln3_b, t);
    GTC(t, wl1, lin1_b, nullptr, h1, MTOT, F8, CCH, 0, 0);
    geglu_kernel<<<(unsigned)(((size_t)MTOT * F4 + 255) / 256), 256>>>(h1, gg);
    GTC(gg, wl2, lin2_b, xseq, xseq, MTOT, CCH, F4, 0, 1);

    // ---- output conv + long residual ----
    GTC(xseq, wfin, co_b, x, out, MTOT, CCH, CCH, 1, 0);
}